// round 5
// baseline (speedup 1.0000x reference)
#include <cuda_runtime.h>
#include <cuda_bf16.h>
#include <cstdint>
#include <math.h>

// ---------------- problem constants ----------------
#define Bc 4
#define Tc 8
#define Cc 256
#define Nc 196
#define Hc 4
#define Sc (Tc * Nc)          // 1568
#define BHc (Bc * Hc)         // 16
#define MSc (Bc * Sc)         // 6272
#define EPSc 1e-5f
#define NTILE (13 * 13)       // score tiles per bh

typedef __nv_bfloat16 bf16;

// ---------------- scratch (device globals) ----------------------------------
__device__ bf16  g_Xhi[Bc * Sc * Cc],  g_Xlo[Bc * Sc * Cc];
__device__ bf16  g_Wqhi[Hc * Cc * Cc], g_Wqlo[Hc * Cc * Cc];
__device__ bf16  g_Wkhi[Hc * Cc * Cc], g_Wklo[Hc * Cc * Cc];
__device__ bf16  g_Wvhi[Hc * Cc * Cc], g_Wvlo[Hc * Cc * Cc];
__device__ bf16  g_Wohi[Cc * Cc],      g_Wolo[Cc * Cc];
__device__ bf16  gQhi[BHc * Sc * Cc],  gQlo[BHc * Sc * Cc];
__device__ bf16  gKhi[BHc * Sc * Cc],  gKlo[BHc * Sc * Cc];
__device__ float g_Vf32[BHc * Sc * Cc];
__device__ bf16  gVThi[BHc * Cc * Sc], gVTlo[BHc * Cc * Sc];
__device__ float g_S[(size_t)BHc * Sc * Sc];            // fp32 scores
__device__ bf16  gPhi[(size_t)BHc * Sc * Sc], gPlo[(size_t)BHc * Sc * Sc];
__device__ float g_CTXH[BHc * Sc * Cc];                 // ctx k-split half 0
__device__ float g_CTXH2[BHc * Sc * Cc];                // ctx k-split half 1
__device__ bf16  gCThi[Bc * Sc * Cc],  gCTlo[Bc * Sc * Cc];
__device__ float g_part[BHc * NTILE * 2];
__device__ float g_mean[BHc], g_rstd[BHc];

// ---------------- PTX helpers ------------------------------------------------
__device__ __forceinline__ uint32_t cvta_smem(const void* p) {
    uint32_t a;
    asm("{ .reg .u64 t; cvta.to.shared.u64 t, %1; cvt.u32.u64 %0, t; }" : "=r"(a) : "l"(p));
    return a;
}

__device__ __forceinline__ void ldsm_x4(uint32_t& r0, uint32_t& r1, uint32_t& r2,
                                        uint32_t& r3, uint32_t addr) {
    asm volatile("ldmatrix.sync.aligned.m8n8.x4.shared.b16 {%0,%1,%2,%3}, [%4];"
                 : "=r"(r0), "=r"(r1), "=r"(r2), "=r"(r3) : "r"(addr));
}

__device__ __forceinline__ void mma16816(float* d, const uint32_t* a, const uint32_t* b) {
    asm volatile("mma.sync.aligned.m16n8k16.row.col.f32.bf16.bf16.f32 "
                 "{%0,%1,%2,%3}, {%4,%5,%6,%7}, {%8,%9}, {%0,%1,%2,%3};"
                 : "+f"(d[0]), "+f"(d[1]), "+f"(d[2]), "+f"(d[3])
                 : "r"(a[0]), "r"(a[1]), "r"(a[2]), "r"(a[3]), "r"(b[0]), "r"(b[1]));
}

__device__ __forceinline__ void cp16(uint32_t dst, const void* src, bool v) {
    asm volatile("cp.async.cg.shared.global [%0], [%1], 16, %2;"
                 :: "r"(dst), "l"(src), "r"(v ? 16u : 0u) : "memory");
}

// ---------------- generic 128x128 bf16-split HMMA GEMM (pipelined) -----------
// NT form: C[m,n] = alpha * sum_k A[m,k]*B[n,k]; A,B row-major (k contiguous)
#define EPI_F32    0
#define EPI_SCORES 1
#define EPI_SPLIT  2

#define KCH 32
#define ROWB 80                       // 64B data + 16B pad (conflict-free LDSM)
#define ST_ARR (128 * ROWB)           // 10240 B per operand array per stage
#define ST_BYTES (4 * ST_ARR)         // 40960 B per stage
#define SM_ST 128                     // stage base offset (red lives at 0)
#define SMEM_GEMM (SM_ST + 2 * ST_BYTES)

static __device__ __forceinline__ void gemm_body(
        const bf16* __restrict__ Ahi, const bf16* __restrict__ Alo,
        const bf16* __restrict__ Bhi, const bf16* __restrict__ Blo,
        int M, int N, int K, int lda, int ldb,
        int m0, int n0, int epi, float alpha,
        float* Cf, bf16* Chi, bf16* Clo, int ldc, float* part) {
    extern __shared__ char smem[];
    float* red = (float*)smem;
    const int tid = threadIdx.x;            // 256 threads, 8 warps
    const int wid = tid >> 5, lane = tid & 31;
    const int wm = (wid >> 1) * 32, wn = (wid & 1) * 64;
    const uint32_t sb = cvta_smem(smem);

    float acc[2][8][4];
#pragma unroll
    for (int i = 0; i < 2; i++)
#pragma unroll
        for (int j = 0; j < 8; j++)
#pragma unroll
            for (int e = 0; e < 4; e++) acc[i][j][e] = 0.f;

    const int nch = K / KCH;   // K is a multiple of 32 for all call sites

    // --- cp.async issue of one K32 chunk into stage (ch&1) ---
    #define ISSUE(ch)                                                            \
    do {                                                                         \
        const int k0_ = (ch) * KCH;                                              \
        const uint32_t stb_ = sb + SM_ST + ((ch) & 1) * ST_BYTES;                \
        _Pragma("unroll")                                                        \
        for (int l = 0; l < 8; l++) {                                            \
            int it = tid + l * 256;                                              \
            int arr = it >> 9;                                                   \
            int rem = it & 511;                                                  \
            int r = rem >> 2, u = rem & 3;                                       \
            const bf16* src;                                                     \
            bool valid;                                                          \
            if (arr < 2) {                                                       \
                valid = (m0 + r) < M;                                            \
                size_t ro = valid ? (size_t)(m0 + r) * lda : 0;                  \
                src = (arr == 0 ? Ahi : Alo) + ro + k0_ + u * 8;                 \
            } else {                                                             \
                valid = (n0 + r) < N;                                            \
                size_t ro = valid ? (size_t)(n0 + r) * ldb : 0;                  \
                src = (arr == 2 ? Bhi : Blo) + ro + k0_ + u * 8;                 \
            }                                                                    \
            cp16(stb_ + arr * ST_ARR + r * ROWB + u * 16, src, valid);           \
        }                                                                        \
    } while (0)

    ISSUE(0);
    asm volatile("cp.async.commit_group;" ::: "memory");

    const uint32_t lrow = (uint32_t)(lane & 15);
    const uint32_t lu = (uint32_t)(lane >> 4);

    for (int ch = 0; ch < nch; ch++) {
        if (ch + 1 < nch) ISSUE(ch + 1);
        asm volatile("cp.async.commit_group;" ::: "memory");
        asm volatile("cp.async.wait_group 1;" ::: "memory");
        __syncthreads();

        const uint32_t stb = sb + SM_ST + (ch & 1) * ST_BYTES;
#pragma unroll
        for (int ku = 0; ku < 2; ku++) {
            uint32_t af[2][4];      // 2 im x 4 regs (one hl term at a time)
            uint32_t bfr[8][2];     // 8 n8 tiles x 2 regs

            // --- a <- Ahi, b <- Bhi : term hi*hi ---
#pragma unroll
            for (int im = 0; im < 2; im++) {
                uint32_t addr = stb + (wm + im * 16 + lrow) * ROWB + ku * 32 + lu * 16;
                ldsm_x4(af[im][0], af[im][1], af[im][2], af[im][3], addr);
            }
#pragma unroll
            for (int inn = 0; inn < 4; inn++) {
                uint32_t addr = stb + 2 * ST_ARR +
                                (wn + inn * 16 + lrow) * ROWB + ku * 32 + lu * 16;
                uint32_t r0, r1, r2, r3;
                ldsm_x4(r0, r1, r2, r3, addr);
                bfr[inn * 2 + 0][0] = r0; bfr[inn * 2 + 0][1] = r2;
                bfr[inn * 2 + 1][0] = r1; bfr[inn * 2 + 1][1] = r3;
            }
#pragma unroll
            for (int im = 0; im < 2; im++)
#pragma unroll
                for (int jn = 0; jn < 8; jn++) mma16816(acc[im][jn], af[im], bfr[jn]);

            // --- a <- Alo : term lo*hi ---
#pragma unroll
            for (int im = 0; im < 2; im++) {
                uint32_t addr = stb + ST_ARR + (wm + im * 16 + lrow) * ROWB + ku * 32 + lu * 16;
                ldsm_x4(af[im][0], af[im][1], af[im][2], af[im][3], addr);
            }
#pragma unroll
            for (int im = 0; im < 2; im++)
#pragma unroll
                for (int jn = 0; jn < 8; jn++) mma16816(acc[im][jn], af[im], bfr[jn]);

            // --- a <- Ahi, b <- Blo : term hi*lo ---
#pragma unroll
            for (int im = 0; im < 2; im++) {
                uint32_t addr = stb + (wm + im * 16 + lrow) * ROWB + ku * 32 + lu * 16;
                ldsm_x4(af[im][0], af[im][1], af[im][2], af[im][3], addr);
            }
#pragma unroll
            for (int inn = 0; inn < 4; inn++) {
                uint32_t addr = stb + 3 * ST_ARR +
                                (wn + inn * 16 + lrow) * ROWB + ku * 32 + lu * 16;
                uint32_t r0, r1, r2, r3;
                ldsm_x4(r0, r1, r2, r3, addr);
                bfr[inn * 2 + 0][0] = r0; bfr[inn * 2 + 0][1] = r2;
                bfr[inn * 2 + 1][0] = r1; bfr[inn * 2 + 1][1] = r3;
            }
#pragma unroll
            for (int im = 0; im < 2; im++)
#pragma unroll
                for (int jn = 0; jn < 8; jn++) mma16816(acc[im][jn], af[im], bfr[jn]);
        }
        __syncthreads();   // stage (ch&1) reused by ISSUE at iteration ch+1
    }
    #undef ISSUE

    // ---------------- epilogue ----------------
    float psum = 0.f, psq = 0.f;
#pragma unroll
    for (int im = 0; im < 2; im++) {
#pragma unroll
        for (int jn = 0; jn < 8; jn++) {
            int r0 = m0 + wm + im * 16 + (lane >> 2);
            int cn = n0 + wn + jn * 8 + (lane & 3) * 2;
            bool cv = cn < N;
            float v0 = acc[im][jn][0] * alpha, v1 = acc[im][jn][1] * alpha;
            float v2 = acc[im][jn][2] * alpha, v3 = acc[im][jn][3] * alpha;
            if (epi == EPI_SPLIT) {
                if (cv && r0 < M) {
                    bf16 h0 = __float2bfloat16(v0), h1 = __float2bfloat16(v1);
                    __nv_bfloat162 hh; hh.x = h0; hh.y = h1;
                    __nv_bfloat162 ll;
                    ll.x = __float2bfloat16(v0 - __bfloat162float(h0));
                    ll.y = __float2bfloat16(v1 - __bfloat162float(h1));
                    *(__nv_bfloat162*)&Chi[(size_t)r0 * ldc + cn] = hh;
                    *(__nv_bfloat162*)&Clo[(size_t)r0 * ldc + cn] = ll;
                }
                if (cv && r0 + 8 < M) {
                    bf16 h2 = __float2bfloat16(v2), h3 = __float2bfloat16(v3);
                    __nv_bfloat162 hh; hh.x = h2; hh.y = h3;
                    __nv_bfloat162 ll;
                    ll.x = __float2bfloat16(v2 - __bfloat162float(h2));
                    ll.y = __float2bfloat16(v3 - __bfloat162float(h3));
                    *(__nv_bfloat162*)&Chi[(size_t)(r0 + 8) * ldc + cn] = hh;
                    *(__nv_bfloat162*)&Clo[(size_t)(r0 + 8) * ldc + cn] = ll;
                }
            } else {
                if (cv && r0 < M) {
                    *(float2*)&Cf[(size_t)r0 * ldc + cn] = make_float2(v0, v1);
                    psum += v0 + v1; psq += v0 * v0 + v1 * v1;
                }
                if (cv && r0 + 8 < M) {
                    *(float2*)&Cf[(size_t)(r0 + 8) * ldc + cn] = make_float2(v2, v3);
                    psum += v2 + v3; psq += v2 * v2 + v3 * v3;
                }
            }
        }
    }
    if (epi == EPI_SCORES) {
#pragma unroll
        for (int o = 16; o; o >>= 1) {
            psum += __shfl_xor_sync(0xffffffffu, psum, o);
            psq  += __shfl_xor_sync(0xffffffffu, psq,  o);
        }
        if (lane == 0) { red[wid] = psum; red[8 + wid] = psq; }
        __syncthreads();
        if (tid == 0) {
            float s = 0.f, q = 0.f;
#pragma unroll
            for (int w = 0; w < 8; w++) { s += red[w]; q += red[8 + w]; }
            part[0] = s;
            part[1] = q;
        }
    }
}

// ---------------- GEMM wrappers ----------------------------------------------
__global__ __launch_bounds__(256) void k_gemm_qkv() {
    int z = blockIdx.z;
    int bh = z / 3, which = z % 3;
    int b = bh / Hc, h = bh % Hc;
    const bf16* Ah = g_Xhi + (size_t)b * Sc * Cc;
    const bf16* Al = g_Xlo + (size_t)b * Sc * Cc;
    const bf16 *Bh, *Bl;
    if (which == 0)      { Bh = g_Wqhi + (size_t)h * Cc * Cc; Bl = g_Wqlo + (size_t)h * Cc * Cc; }
    else if (which == 1) { Bh = g_Wkhi + (size_t)h * Cc * Cc; Bl = g_Wklo + (size_t)h * Cc * Cc; }
    else                 { Bh = g_Wvhi + (size_t)h * Cc * Cc; Bl = g_Wvlo + (size_t)h * Cc * Cc; }
    int m0 = blockIdx.x * 128, n0 = blockIdx.y * 128;
    if (which == 2) {
        gemm_body(Ah, Al, Bh, Bl, Sc, Cc, Cc, Cc, Cc, m0, n0, EPI_F32, 1.f,
                  g_Vf32 + (size_t)bh * Sc * Cc, nullptr, nullptr, Cc, nullptr);
    } else {
        bf16* Chi = (which == 0 ? gQhi : gKhi) + (size_t)bh * Sc * Cc;
        bf16* Clo = (which == 0 ? gQlo : gKlo) + (size_t)bh * Sc * Cc;
        gemm_body(Ah, Al, Bh, Bl, Sc, Cc, Cc, Cc, Cc, m0, n0, EPI_SPLIT, 1.f,
                  nullptr, Chi, Clo, Cc, nullptr);
    }
}

__global__ __launch_bounds__(256) void k_gemm_sc() {
    int bh = blockIdx.z;
    int m0 = blockIdx.x * 128, n0 = blockIdx.y * 128;
    float alpha = rsqrtf((float)Sc);
    gemm_body(gQhi + (size_t)bh * Sc * Cc, gQlo + (size_t)bh * Sc * Cc,
              gKhi + (size_t)bh * Sc * Cc, gKlo + (size_t)bh * Sc * Cc,
              Sc, Sc, Cc, Cc, Cc, m0, n0, EPI_SCORES, alpha,
              g_S + (size_t)bh * Sc * Sc, nullptr, nullptr, Sc,
              &g_part[((size_t)bh * NTILE + blockIdx.y * 13 + blockIdx.x) * 2]);
}

// ctx = probs @ V, K-split into [0,768) and [768,1568)
__global__ __launch_bounds__(256) void k_gemm_ctx() {
    int z = blockIdx.z;
    int bh = z >> 1, half = z & 1;
    int koff = half ? 768 : 0;
    int klen = half ? (Sc - 768) : 768;     // 800 / 768, both multiples of 32
    int m0 = blockIdx.x * 128, n0 = blockIdx.y * 128;
    float* outbuf = (half ? g_CTXH2 : g_CTXH) + (size_t)bh * Sc * Cc;
    gemm_body(gPhi + (size_t)bh * Sc * Sc + koff, gPlo + (size_t)bh * Sc * Sc + koff,
              gVThi + (size_t)bh * Cc * Sc + koff, gVTlo + (size_t)bh * Cc * Sc + koff,
              Sc, Cc, klen, Sc, Sc, m0, n0, EPI_F32, 1.f,
              outbuf, nullptr, nullptr, Cc, nullptr);
}

__global__ __launch_bounds__(256) void k_gemm_o(float* __restrict__ out) {
    int m0 = blockIdx.x * 128, n0 = blockIdx.y * 128;
    gemm_body(gCThi, gCTlo, g_Wohi, g_Wolo,
              MSc, Cc, Cc, Cc, Cc, m0, n0, EPI_F32, 1.f,
              out, nullptr, nullptr, Cc, nullptr);
}

// ---------------- elementwise / reshape kernels -------------------------------
__global__ void k_transpose(const float* __restrict__ emb) {
    __shared__ float tile[32][33];
    int bt = blockIdx.z;
    int n0 = blockIdx.x * 32, c0 = blockIdx.y * 32;
    int x = threadIdx.x, y = threadIdx.y;
    const float* src = emb + (size_t)bt * Cc * Nc;
    bf16* dh = g_Xhi + (size_t)bt * Nc * Cc;
    bf16* dl = g_Xlo + (size_t)bt * Nc * Cc;
#pragma unroll
    for (int i = 0; i < 32; i += 8) {
        int c = c0 + y + i, n = n0 + x;
        tile[y + i][x] = (n < Nc) ? src[c * Nc + n] : 0.f;
    }
    __syncthreads();
#pragma unroll
    for (int i = 0; i < 32; i += 8) {
        int n = n0 + y + i, c = c0 + x;
        if (n < Nc) {
            float v = tile[x][y + i];
            bf16 h = __float2bfloat16(v);
            dh[n * Cc + c] = h;
            dl[n * Cc + c] = __float2bfloat16(v - __bfloat162float(h));
        }
    }
}

__global__ void k_cvt(const float* __restrict__ s, bf16* __restrict__ h,
                      bf16* __restrict__ l, int n) {
    int i = blockIdx.x * 256 + threadIdx.x;
    if (i < n) {
        float v = s[i];
        bf16 x = __float2bfloat16(v);
        h[i] = x;
        l[i] = __float2bfloat16(v - __bfloat162float(x));
    }
}

// V [bh][S][C] fp32 -> VT [bh][C][S] bf16 hi/lo
__global__ void k_vtrans() {
    __shared__ float t[32][33];
    int bh = blockIdx.z;
    int s0 = blockIdx.x * 32, c0 = blockIdx.y * 32;
    int x = threadIdx.x, y = threadIdx.y;
    const float* V = g_Vf32 + (size_t)bh * Sc * Cc;
    bf16* th = gVThi + (size_t)bh * Cc * Sc;
    bf16* tl = gVTlo + (size_t)bh * Cc * Sc;
#pragma unroll
    for (int i = 0; i < 32; i += 8)
        t[y + i][x] = V[(size_t)(s0 + y + i) * Cc + c0 + x];
    __syncthreads();
#pragma unroll
    for (int i = 0; i < 32; i += 8) {
        float v = t[x][y + i];
        bf16 h = __float2bfloat16(v);
        th[(size_t)(c0 + y + i) * Sc + s0 + x] = h;
        tl[(size_t)(c0 + y + i) * Sc + s0 + x] = __float2bfloat16(v - __bfloat162float(h));
    }
}

__global__ __launch_bounds__(256) void k_stats2() {
    int bh = blockIdx.x;
    float s = 0.f, q = 0.f;
    for (int i = threadIdx.x; i < NTILE; i += 256) {
        s += g_part[((size_t)bh * NTILE + i) * 2 + 0];
        q += g_part[((size_t)bh * NTILE + i) * 2 + 1];
    }
    __shared__ float ss[256], sq[256];
    int tid = threadIdx.x;
    ss[tid] = s; sq[tid] = q;
    __syncthreads();
    for (int st = 128; st > 0; st >>= 1) {
        if (tid < st) { ss[tid] += ss[tid + st]; sq[tid] += sq[tid + st]; }
        __syncthreads();
    }
    if (tid == 0) {
        float cnt = (float)Sc * (float)Sc;
        float mean = ss[0] / cnt;
        float var = sq[0] / cnt - mean * mean;
        g_mean[bh] = mean;
        g_rstd[bh] = rsqrtf(var + EPSc);
    }
}

__global__ __launch_bounds__(256) void k_softmax() {
    int row = blockIdx.x;
    int bh = row / Sc;
    size_t base = (size_t)row * Sc;
    __shared__ float buf[Sc];
    __shared__ float red[256];
    int tid = threadIdx.x;
    float mean = g_mean[bh], rstd = g_rstd[bh];

    float lmax = -3.4e38f;
    for (int i = tid; i < Sc; i += 256) {
        float v = (g_S[base + i] - mean) * rstd;
        buf[i] = v;
        lmax = fmaxf(lmax, v);
    }
    red[tid] = lmax;
    __syncthreads();
    for (int st = 128; st > 0; st >>= 1) {
        if (tid < st) red[tid] = fmaxf(red[tid], red[tid + st]);
        __syncthreads();
    }
    float rmax = red[0];
    __syncthreads();

    float lsum = 0.f;
    for (int i = tid; i < Sc; i += 256) {
        float e = __expf(buf[i] - rmax);
        buf[i] = e;
        lsum += e;
    }
    red[tid] = lsum;
    __syncthreads();
    for (int st = 128; st > 0; st >>= 1) {
        if (tid < st) red[tid] += red[tid + st];
        __syncthreads();
    }
    float inv = 1.f / red[0];
    __syncthreads();

    for (int i = tid; i < Sc; i += 256) {
        float p = buf[i] * inv;
        bf16 h = __float2bfloat16(p);
        gPhi[base + i] = h;
        gPlo[base + i] = __float2bfloat16(p - __bfloat162float(h));
    }
}

__global__ __launch_bounds__(256) void k_hmean() {
    int idx = blockIdx.x * 256 + threadIdx.x;
    if (idx >= Bc * Sc * Cc) return;
    int b = idx / (Sc * Cc);
    int rem = idx % (Sc * Cc);
    float s = 0.f;
#pragma unroll
    for (int h = 0; h < Hc; h++) {
        size_t o = ((size_t)(b * Hc + h) * Sc * Cc) + rem;
        s += g_CTXH[o] + g_CTXH2[o];
    }
    float v = 0.25f * s;
    bf16 hh = __float2bfloat16(v);
    gCThi[idx] = hh;
    gCTlo[idx] = __float2bfloat16(v - __bfloat162float(hh));
}

// ---------------- launch -------------------------------------------------------
extern "C" void kernel_launch(void* const* d_in, const int* in_sizes, int n_in,
                              void* d_out, int out_size) {
    const float* emb = (const float*)d_in[0];
    const float* Wq  = (const float*)d_in[1];
    const float* Wk  = (const float*)d_in[2];
    const float* Wv  = (const float*)d_in[3];
    const float* Wo  = (const float*)d_in[4];
    float* out = (float*)d_out;

    static bool attr_done = false;
    if (!attr_done) {
        cudaFuncSetAttribute(k_gemm_qkv, cudaFuncAttributeMaxDynamicSharedMemorySize, SMEM_GEMM);
        cudaFuncSetAttribute(k_gemm_sc,  cudaFuncAttributeMaxDynamicSharedMemorySize, SMEM_GEMM);
        cudaFuncSetAttribute(k_gemm_ctx, cudaFuncAttributeMaxDynamicSharedMemorySize, SMEM_GEMM);
        cudaFuncSetAttribute(k_gemm_o,   cudaFuncAttributeMaxDynamicSharedMemorySize, SMEM_GEMM);
        attr_done = true;
    }

    // input conversions
    k_transpose<<<dim3(7, 8, Bc * Tc), dim3(32, 8)>>>(emb);
    {
        bf16 *h, *l;
        cudaGetSymbolAddress((void**)&h, g_Wqhi); cudaGetSymbolAddress((void**)&l, g_Wqlo);
        k_cvt<<<(Hc * Cc * Cc + 255) / 256, 256>>>(Wq, h, l, Hc * Cc * Cc);
        cudaGetSymbolAddress((void**)&h, g_Wkhi); cudaGetSymbolAddress((void**)&l, g_Wklo);
        k_cvt<<<(Hc * Cc * Cc + 255) / 256, 256>>>(Wk, h, l, Hc * Cc * Cc);
        cudaGetSymbolAddress((void**)&h, g_Wvhi); cudaGetSymbolAddress((void**)&l, g_Wvlo);
        k_cvt<<<(Hc * Cc * Cc + 255) / 256, 256>>>(Wv, h, l, Hc * Cc * Cc);
        cudaGetSymbolAddress((void**)&h, g_Wohi); cudaGetSymbolAddress((void**)&l, g_Wolo);
        k_cvt<<<(Cc * Cc + 255) / 256, 256>>>(Wo, h, l, Cc * Cc);
    }

    // QKV projections (HMMA, bf16 split, pipelined)
    k_gemm_qkv<<<dim3(13, 2, 3 * BHc), 256, SMEM_GEMM>>>();
    // V transpose+convert for ctx GEMM B-operand
    k_vtrans<<<dim3(49, 8, BHc), dim3(32, 8)>>>();
    // scores + fused stage-1 instance-norm stats
    k_gemm_sc<<<dim3(13, 13, BHc), 256, SMEM_GEMM>>>();
    k_stats2<<<BHc, 256>>>();
    // norm + softmax -> bf16 hi/lo probs
    k_softmax<<<BHc * Sc, 256>>>();
    // ctx = probs @ V (K-split x2)
    k_gemm_ctx<<<dim3(13, 2, BHc * 2), 256, SMEM_GEMM>>>();
    // head mean -> bf16 hi/lo
    k_hmean<<<(Bc * Sc * Cc + 255) / 256, 256>>>();
    // output projection into d_out
    k_gemm_o<<<dim3(49, 2, 1), 256, SMEM_GEMM>>>(out);
}

// round 6
// speedup vs baseline: 1.2450x; 1.2450x over previous
#include <cuda_runtime.h>
#include <cuda_fp16.h>
#include <cstdint>
#include <math.h>

// ---------------- problem constants ----------------
#define Bc 4
#define Tc 8
#define Cc 256
#define Nc 196
#define Hc 4
#define Sc (Tc * Nc)          // 1568
#define BHc (Bc * Hc)         // 16
#define EPSc 1e-5f
#define NTILE (13 * 13)       // score tiles per bh
#define LOG2E 1.4426950408889634f

typedef __half fp16;

// ---------------- scratch (device globals) ----------------------------------
__device__ fp16  g_Xhi[Bc * Sc * Cc],  g_Xlo[Bc * Sc * Cc];
__device__ fp16  g_Ghi[Hc * Cc * Cc],  g_Glo[Hc * Cc * Cc];   // G_h[a,b]=sum_d Wk[d,a]Wq[d,b]
__device__ fp16  g_Uhi[Hc * Cc * Cc],  g_Ulo[Hc * Cc * Cc];   // U_h[a,b]=sum_d Wo[a,d]Wv[d,b]
__device__ fp16  gYhi[BHc * Sc * Cc],  gYlo[BHc * Sc * Cc];   // Y = X G^T
__device__ float g_Zf32[BHc * Sc * Cc];                        // Z = X U^T
__device__ fp16  gZThi[BHc * Cc * Sc], gZTlo[BHc * Cc * Sc];
__device__ float g_S[(size_t)BHc * Sc * Sc];                   // fp32 scores
__device__ fp16  gP[(size_t)BHc * Sc * Sc];                    // unnormalized probs (fp16)
__device__ float g_CTXH[BHc * Sc * Cc];                        // ctx k-half 0
__device__ float g_CTXH2[BHc * Sc * Cc];                       // ctx k-half 1
__device__ float g_invsum[BHc * Sc];
__device__ float g_part[BHc * NTILE * 2];
__device__ float g_mean[BHc], g_rstd[BHc];

// ---------------- PTX helpers ------------------------------------------------
__device__ __forceinline__ uint32_t cvta_smem(const void* p) {
    uint32_t a;
    asm("{ .reg .u64 t; cvta.to.shared.u64 t, %1; cvt.u32.u64 %0, t; }" : "=r"(a) : "l"(p));
    return a;
}

__device__ __forceinline__ void ldsm_x4(uint32_t& r0, uint32_t& r1, uint32_t& r2,
                                        uint32_t& r3, uint32_t addr) {
    asm volatile("ldmatrix.sync.aligned.m8n8.x4.shared.b16 {%0,%1,%2,%3}, [%4];"
                 : "=r"(r0), "=r"(r1), "=r"(r2), "=r"(r3) : "r"(addr));
}

__device__ __forceinline__ void mma16816(float* d, const uint32_t* a, const uint32_t* b) {
    asm volatile("mma.sync.aligned.m16n8k16.row.col.f32.f16.f16.f32 "
                 "{%0,%1,%2,%3}, {%4,%5,%6,%7}, {%8,%9}, {%0,%1,%2,%3};"
                 : "+f"(d[0]), "+f"(d[1]), "+f"(d[2]), "+f"(d[3])
                 : "r"(a[0]), "r"(a[1]), "r"(a[2]), "r"(a[3]), "r"(b[0]), "r"(b[1]));
}

__device__ __forceinline__ void cp16(uint32_t dst, const void* src, bool v) {
    asm volatile("cp.async.cg.shared.global [%0], [%1], 16, %2;"
                 :: "r"(dst), "l"(src), "r"(v ? 16u : 0u) : "memory");
}

__device__ __forceinline__ void split16(float v, fp16& h, fp16& l) {
    h = __float2half(v);
    l = __float2half(v - __half2float(h));
}

// ---------------- generic 128x128 fp16-split HMMA GEMM (pipelined) -----------
// NT form: C[m,n] = alpha * sum_k A[m,k]*B[n,k]; A,B row-major (k contiguous)
#define EPI_F32    0
#define EPI_SCORES 1
#define EPI_SPLIT  2

#define KCH 32
#define ROWB 80                       // 64B data + 16B pad (conflict-free LDSM)
#define ST_ARR (128 * ROWB)           // 10240 B per operand array per stage
#define ST_BYTES (4 * ST_ARR)         // 40960 B per stage
#define SM_ST 128
#define SMEM_GEMM (SM_ST + 2 * ST_BYTES)

template <bool SPLITA>
static __device__ __forceinline__ void gemm_body(
        const fp16* __restrict__ Ahi, const fp16* __restrict__ Alo,
        const fp16* __restrict__ Bhi, const fp16* __restrict__ Blo,
        int M, int N, int K, int lda, int ldb,
        int m0, int n0, int epi, float alpha,
        float* Cf, fp16* Chi, fp16* Clo, int ldc, float* part) {
    extern __shared__ char smem[];
    float* red = (float*)smem;
    const int tid = threadIdx.x;            // 256 threads, 8 warps
    const int wid = tid >> 5, lane = tid & 31;
    const int wm = (wid >> 1) * 32, wn = (wid & 1) * 64;
    const uint32_t sb = cvta_smem(smem);

    float acc[2][8][4];
#pragma unroll
    for (int i = 0; i < 2; i++)
#pragma unroll
        for (int j = 0; j < 8; j++)
#pragma unroll
            for (int e = 0; e < 4; e++) acc[i][j][e] = 0.f;

    const int nch = K / KCH;

    #define ISSUE(ch)                                                            \
    do {                                                                         \
        const int k0_ = (ch) * KCH;                                              \
        const uint32_t stb_ = sb + SM_ST + ((ch) & 1) * ST_BYTES;                \
        const int NL = SPLITA ? 8 : 6;                                           \
        _Pragma("unroll")                                                        \
        for (int l = 0; l < NL; l++) {                                           \
            int it = tid + l * 256;                                              \
            int idx = it >> 9;                                                   \
            int arr = SPLITA ? idx : (idx == 0 ? 0 : idx + 1);                   \
            int rem = it & 511;                                                  \
            int r = rem >> 2, u = rem & 3;                                       \
            const fp16* src;                                                     \
            bool valid;                                                          \
            if (arr < 2) {                                                       \
                valid = (m0 + r) < M;                                            \
                size_t ro = valid ? (size_t)(m0 + r) * lda : 0;                  \
                src = (arr == 0 ? Ahi : Alo) + ro + k0_ + u * 8;                 \
            } else {                                                             \
                valid = (n0 + r) < N;                                            \
                size_t ro = valid ? (size_t)(n0 + r) * ldb : 0;                  \
                src = (arr == 2 ? Bhi : Blo) + ro + k0_ + u * 8;                 \
            }                                                                    \
            cp16(stb_ + arr * ST_ARR + r * ROWB + u * 16, src, valid);           \
        }                                                                        \
    } while (0)

    ISSUE(0);
    asm volatile("cp.async.commit_group;" ::: "memory");

    const uint32_t lrow = (uint32_t)(lane & 15);
    const uint32_t lu = (uint32_t)(lane >> 4);

    for (int ch = 0; ch < nch; ch++) {
        if (ch + 1 < nch) ISSUE(ch + 1);
        asm volatile("cp.async.commit_group;" ::: "memory");
        asm volatile("cp.async.wait_group 1;" ::: "memory");
        __syncthreads();

        const uint32_t stb = sb + SM_ST + (ch & 1) * ST_BYTES;
#pragma unroll
        for (int ku = 0; ku < 2; ku++) {
            uint32_t af[2][4];
            uint32_t bfr[8][2];

            // pass 1: Ahi x Bhi
#pragma unroll
            for (int im = 0; im < 2; im++) {
                uint32_t addr = stb + (wm + im * 16 + lrow) * ROWB + ku * 32 + lu * 16;
                ldsm_x4(af[im][0], af[im][1], af[im][2], af[im][3], addr);
            }
#pragma unroll
            for (int inn = 0; inn < 4; inn++) {
                uint32_t addr = stb + 2 * ST_ARR +
                                (wn + inn * 16 + lrow) * ROWB + ku * 32 + lu * 16;
                uint32_t r0, r1, r2, r3;
                ldsm_x4(r0, r1, r2, r3, addr);
                bfr[inn * 2 + 0][0] = r0; bfr[inn * 2 + 0][1] = r2;
                bfr[inn * 2 + 1][0] = r1; bfr[inn * 2 + 1][1] = r3;
            }
#pragma unroll
            for (int im = 0; im < 2; im++)
#pragma unroll
                for (int jn = 0; jn < 8; jn++) mma16816(acc[im][jn], af[im], bfr[jn]);

            if (SPLITA) {
                // pass 2: Alo x Bhi
#pragma unroll
                for (int im = 0; im < 2; im++) {
                    uint32_t addr = stb + ST_ARR + (wm + im * 16 + lrow) * ROWB + ku * 32 + lu * 16;
                    ldsm_x4(af[im][0], af[im][1], af[im][2], af[im][3], addr);
                }
#pragma unroll
                for (int im = 0; im < 2; im++)
#pragma unroll
                    for (int jn = 0; jn < 8; jn++) mma16816(acc[im][jn], af[im], bfr[jn]);
                // reload Ahi for pass 3
#pragma unroll
                for (int im = 0; im < 2; im++) {
                    uint32_t addr = stb + (wm + im * 16 + lrow) * ROWB + ku * 32 + lu * 16;
                    ldsm_x4(af[im][0], af[im][1], af[im][2], af[im][3], addr);
                }
            }

            // pass 3 (or 2): Ahi x Blo
#pragma unroll
            for (int inn = 0; inn < 4; inn++) {
                uint32_t addr = stb + 3 * ST_ARR +
                                (wn + inn * 16 + lrow) * ROWB + ku * 32 + lu * 16;
                uint32_t r0, r1, r2, r3;
                ldsm_x4(r0, r1, r2, r3, addr);
                bfr[inn * 2 + 0][0] = r0; bfr[inn * 2 + 0][1] = r2;
                bfr[inn * 2 + 1][0] = r1; bfr[inn * 2 + 1][1] = r3;
            }
#pragma unroll
            for (int im = 0; im < 2; im++)
#pragma unroll
                for (int jn = 0; jn < 8; jn++) mma16816(acc[im][jn], af[im], bfr[jn]);
        }
        __syncthreads();
    }
    #undef ISSUE

    // ---------------- epilogue ----------------
    float psum = 0.f, psq = 0.f;
#pragma unroll
    for (int im = 0; im < 2; im++) {
#pragma unroll
        for (int jn = 0; jn < 8; jn++) {
            int r0 = m0 + wm + im * 16 + (lane >> 2);
            int cn = n0 + wn + jn * 8 + (lane & 3) * 2;
            bool cv = cn < N;
            float v0 = acc[im][jn][0] * alpha, v1 = acc[im][jn][1] * alpha;
            float v2 = acc[im][jn][2] * alpha, v3 = acc[im][jn][3] * alpha;
            if (epi == EPI_SPLIT) {
                if (cv && r0 < M) {
                    __half2 hh, ll;
                    split16(v0, hh.x, ll.x); split16(v1, hh.y, ll.y);
                    *(__half2*)&Chi[(size_t)r0 * ldc + cn] = hh;
                    *(__half2*)&Clo[(size_t)r0 * ldc + cn] = ll;
                }
                if (cv && r0 + 8 < M) {
                    __half2 hh, ll;
                    split16(v2, hh.x, ll.x); split16(v3, hh.y, ll.y);
                    *(__half2*)&Chi[(size_t)(r0 + 8) * ldc + cn] = hh;
                    *(__half2*)&Clo[(size_t)(r0 + 8) * ldc + cn] = ll;
                }
            } else {
                if (cv && r0 < M) {
                    *(float2*)&Cf[(size_t)r0 * ldc + cn] = make_float2(v0, v1);
                    psum += v0 + v1; psq += v0 * v0 + v1 * v1;
                }
                if (cv && r0 + 8 < M) {
                    *(float2*)&Cf[(size_t)(r0 + 8) * ldc + cn] = make_float2(v2, v3);
                    psum += v2 + v3; psq += v2 * v2 + v3 * v3;
                }
            }
        }
    }
    if (epi == EPI_SCORES) {
#pragma unroll
        for (int o = 16; o; o >>= 1) {
            psum += __shfl_xor_sync(0xffffffffu, psum, o);
            psq  += __shfl_xor_sync(0xffffffffu, psq,  o);
        }
        if (lane == 0) { red[wid] = psum; red[8 + wid] = psq; }
        __syncthreads();
        if (tid == 0) {
            float s = 0.f, q = 0.f;
#pragma unroll
            for (int w = 0; w < 8; w++) { s += red[w]; q += red[8 + w]; }
            part[0] = s;
            part[1] = q;
        }
    }
}

// ---------------- GEMM wrappers ----------------------------------------------
// Y_h = X_b G_h^T (split epi), Z_h = X_b U_h^T (f32 epi)
__global__ __launch_bounds__(256) void k_gemm_yz() {
    int z = blockIdx.z;
    int bh = z >> 1, which = z & 1;
    int b = bh / Hc, h = bh % Hc;
    const fp16* Ah = g_Xhi + (size_t)b * Sc * Cc;
    const fp16* Al = g_Xlo + (size_t)b * Sc * Cc;
    int m0 = blockIdx.x * 128, n0 = blockIdx.y * 128;
    if (which == 0) {
        gemm_body<true>(Ah, Al, g_Ghi + (size_t)h * Cc * Cc, g_Glo + (size_t)h * Cc * Cc,
                        Sc, Cc, Cc, Cc, Cc, m0, n0, EPI_SPLIT, 1.f,
                        nullptr, gYhi + (size_t)bh * Sc * Cc, gYlo + (size_t)bh * Sc * Cc,
                        Cc, nullptr);
    } else {
        gemm_body<true>(Ah, Al, g_Uhi + (size_t)h * Cc * Cc, g_Ulo + (size_t)h * Cc * Cc,
                        Sc, Cc, Cc, Cc, Cc, m0, n0, EPI_F32, 1.f,
                        g_Zf32 + (size_t)bh * Sc * Cc, nullptr, nullptr, Cc, nullptr);
    }
}

// scores = Y X^T / sqrt(S), + fused stage-1 stats
__global__ __launch_bounds__(256) void k_gemm_sc() {
    int bh = blockIdx.z;
    int b = bh / Hc;
    int m0 = blockIdx.x * 128, n0 = blockIdx.y * 128;
    float alpha = rsqrtf((float)Sc);
    gemm_body<true>(gYhi + (size_t)bh * Sc * Cc, gYlo + (size_t)bh * Sc * Cc,
                    g_Xhi + (size_t)b * Sc * Cc, g_Xlo + (size_t)b * Sc * Cc,
                    Sc, Sc, Cc, Cc, Cc, m0, n0, EPI_SCORES, alpha,
                    g_S + (size_t)bh * Sc * Sc, nullptr, nullptr, Sc,
                    &g_part[((size_t)bh * NTILE + blockIdx.y * 13 + blockIdx.x) * 2]);
}

// ctx = P (fp16, 1-term) @ Z^T (hi/lo), K-split into [0,768) and [768,1568)
__global__ __launch_bounds__(256) void k_gemm_ctx() {
    int z = blockIdx.z;
    int bh = z >> 1, half = z & 1;
    int koff = half ? 768 : 0;
    int klen = half ? (Sc - 768) : 768;
    int m0 = blockIdx.x * 128, n0 = blockIdx.y * 128;
    float* outbuf = (half ? g_CTXH2 : g_CTXH) + (size_t)bh * Sc * Cc;
    gemm_body<false>(gP + (size_t)bh * Sc * Sc + koff, nullptr,
                     gZThi + (size_t)bh * Cc * Sc + koff, gZTlo + (size_t)bh * Cc * Sc + koff,
                     Sc, Cc, klen, Sc, Sc, m0, n0, EPI_F32, 1.f,
                     outbuf, nullptr, nullptr, Cc, nullptr);
}

// ---------------- small fp32 weight-product kernels ---------------------------
// G_h[a,b] = sum_d Wk_h[d,a] * Wq_h[d,b]
__global__ __launch_bounds__(256) void k_gmat(const float* __restrict__ Wq,
                                              const float* __restrict__ Wk) {
    int h = blockIdx.z;
    int a0 = blockIdx.x * 16, b0 = blockIdx.y * 16;
    int tx = threadIdx.x & 15, ty = threadIdx.x >> 4;
    __shared__ float A[16][17], B[16][17];
    const float* wk = Wk + (size_t)h * Cc * Cc;
    const float* wq = Wq + (size_t)h * Cc * Cc;
    float acc = 0.f;
    for (int d0 = 0; d0 < Cc; d0 += 16) {
        A[ty][tx] = wk[(d0 + ty) * Cc + a0 + tx];
        B[ty][tx] = wq[(d0 + ty) * Cc + b0 + tx];
        __syncthreads();
#pragma unroll
        for (int dd = 0; dd < 16; dd++) acc += A[dd][ty] * B[dd][tx];
        __syncthreads();
    }
    size_t o = (size_t)h * Cc * Cc + (a0 + ty) * Cc + b0 + tx;
    split16(acc, g_Ghi[o], g_Glo[o]);
}

// U_h[a,b] = sum_d Wo[a,d] * Wv_h[d,b]
__global__ __launch_bounds__(256) void k_umat(const float* __restrict__ Wv,
                                              const float* __restrict__ Wo) {
    int h = blockIdx.z;
    int a0 = blockIdx.x * 16, b0 = blockIdx.y * 16;
    int tx = threadIdx.x & 15, ty = threadIdx.x >> 4;
    __shared__ float A[16][17], B[16][17];
    const float* wv = Wv + (size_t)h * Cc * Cc;
    float acc = 0.f;
    for (int d0 = 0; d0 < Cc; d0 += 16) {
        A[ty][tx] = Wo[(a0 + ty) * Cc + d0 + tx];
        B[ty][tx] = wv[(d0 + ty) * Cc + b0 + tx];
        __syncthreads();
#pragma unroll
        for (int dd = 0; dd < 16; dd++) acc += A[ty][dd] * B[dd][tx];
        __syncthreads();
    }
    size_t o = (size_t)h * Cc * Cc + (a0 + ty) * Cc + b0 + tx;
    split16(acc, g_Uhi[o], g_Ulo[o]);
}

// ---------------- elementwise / reshape kernels -------------------------------
__global__ void k_transpose(const float* __restrict__ emb) {
    __shared__ float tile[32][33];
    int bt = blockIdx.z;
    int n0 = blockIdx.x * 32, c0 = blockIdx.y * 32;
    int x = threadIdx.x, y = threadIdx.y;
    const float* src = emb + (size_t)bt * Cc * Nc;
    fp16* dh = g_Xhi + (size_t)bt * Nc * Cc;
    fp16* dl = g_Xlo + (size_t)bt * Nc * Cc;
#pragma unroll
    for (int i = 0; i < 32; i += 8) {
        int c = c0 + y + i, n = n0 + x;
        tile[y + i][x] = (n < Nc) ? src[c * Nc + n] : 0.f;
    }
    __syncthreads();
#pragma unroll
    for (int i = 0; i < 32; i += 8) {
        int n = n0 + y + i, c = c0 + x;
        if (n < Nc) {
            float v = tile[x][y + i];
            split16(v, dh[n * Cc + c], dl[n * Cc + c]);
        }
    }
}

// Z [bh][S][C] fp32 -> ZT [bh][C][S] fp16 hi/lo
__global__ void k_vtrans() {
    __shared__ float t[32][33];
    int bh = blockIdx.z;
    int s0 = blockIdx.x * 32, c0 = blockIdx.y * 32;
    int x = threadIdx.x, y = threadIdx.y;
    const float* Z = g_Zf32 + (size_t)bh * Sc * Cc;
    fp16* th = gZThi + (size_t)bh * Cc * Sc;
    fp16* tl = gZTlo + (size_t)bh * Cc * Sc;
#pragma unroll
    for (int i = 0; i < 32; i += 8)
        t[y + i][x] = Z[(size_t)(s0 + y + i) * Cc + c0 + x];
    __syncthreads();
#pragma unroll
    for (int i = 0; i < 32; i += 8) {
        float v = t[x][y + i];
        size_t o = (size_t)(c0 + y + i) * Sc + s0 + x;
        split16(v, th[o], tl[o]);
    }
}

__global__ __launch_bounds__(256) void k_stats2() {
    int bh = blockIdx.x;
    float s = 0.f, q = 0.f;
    for (int i = threadIdx.x; i < NTILE; i += 256) {
        s += g_part[((size_t)bh * NTILE + i) * 2 + 0];
        q += g_part[((size_t)bh * NTILE + i) * 2 + 1];
    }
    __shared__ float ss[256], sq[256];
    int tid = threadIdx.x;
    ss[tid] = s; sq[tid] = q;
    __syncthreads();
    for (int st = 128; st > 0; st >>= 1) {
        if (tid < st) { ss[tid] += ss[tid + st]; sq[tid] += sq[tid + st]; }
        __syncthreads();
    }
    if (tid == 0) {
        float cnt = (float)Sc * (float)Sc;
        float mean = ss[0] / cnt;
        float var = sq[0] / cnt - mean * mean;
        g_mean[bh] = mean;
        g_rstd[bh] = rsqrtf(var + EPSc);
    }
}

// single-pass: p = exp(normed score) in fp16 (unnormalized), row sums -> invsum
__global__ __launch_bounds__(256) void k_softmax1() {
    int row = blockIdx.x;                 // 0..BHc*Sc-1
    int bh = row / Sc;
    size_t base = (size_t)row * Sc;
    float aa = g_rstd[bh] * LOG2E;
    float bb = -g_mean[bh] * g_rstd[bh] * LOG2E;
    const float2* src = (const float2*)(g_S + base);
    uint32_t* dst = (uint32_t*)(gP + base);
    float lsum = 0.f;
    for (int pi = threadIdx.x; pi < Sc / 2; pi += 256) {
        float2 s = src[pi];
        float z0 = fmaf(s.x, aa, bb);
        float z1 = fmaf(s.y, aa, bb);
        __half2 zh = __floats2half2_rn(z0, z1);
        uint32_t zi = *reinterpret_cast<uint32_t*>(&zh);
        uint32_t ei;
        asm("ex2.approx.f16x2 %0, %1;" : "=r"(ei) : "r"(zi));
        dst[pi] = ei;
        __half2 eh = *reinterpret_cast<__half2*>(&ei);
        float2 ef = __half22float2(eh);
        lsum += ef.x + ef.y;
    }
    __shared__ float red[256];
    int tid = threadIdx.x;
    red[tid] = lsum;
    __syncthreads();
    for (int st = 128; st > 0; st >>= 1) {
        if (tid < st) red[tid] += red[tid + st];
        __syncthreads();
    }
    if (tid == 0) g_invsum[row] = 1.f / red[0];
}

// out[b,s,d] = (1/H) sum_h invsum[bh,s] * (ctx1+ctx2)[bh,s,d]
__global__ __launch_bounds__(256) void k_out(float* __restrict__ out) {
    int idx = blockIdx.x * 256 + threadIdx.x;
    if (idx >= Bc * Sc * Cc) return;
    int b = idx / (Sc * Cc);
    int rem = idx % (Sc * Cc);
    int s = rem / Cc;
    float v = 0.f;
#pragma unroll
    for (int h = 0; h < Hc; h++) {
        int bh = b * Hc + h;
        size_t o = ((size_t)bh * Sc * Cc) + rem;
        v += (g_CTXH[o] + g_CTXH2[o]) * g_invsum[(size_t)bh * Sc + s];
    }
    out[idx] = 0.25f * v;
}

// ---------------- launch -------------------------------------------------------
extern "C" void kernel_launch(void* const* d_in, const int* in_sizes, int n_in,
                              void* d_out, int out_size) {
    const float* emb = (const float*)d_in[0];
    const float* Wq  = (const float*)d_in[1];
    const float* Wk  = (const float*)d_in[2];
    const float* Wv  = (const float*)d_in[3];
    const float* Wo  = (const float*)d_in[4];
    float* out = (float*)d_out;

    static bool attr_done = false;
    if (!attr_done) {
        cudaFuncSetAttribute(k_gemm_yz,  cudaFuncAttributeMaxDynamicSharedMemorySize, SMEM_GEMM);
        cudaFuncSetAttribute(k_gemm_sc,  cudaFuncAttributeMaxDynamicSharedMemorySize, SMEM_GEMM);
        cudaFuncSetAttribute(k_gemm_ctx, cudaFuncAttributeMaxDynamicSharedMemorySize, SMEM_GEMM);
        attr_done = true;
    }

    // input prep
    k_transpose<<<dim3(7, 8, Bc * Tc), dim3(32, 8)>>>(emb);
    k_gmat<<<dim3(16, 16, Hc), 256>>>(Wq, Wk);
    k_umat<<<dim3(16, 16, Hc), 256>>>(Wv, Wo);

    // Y and Z projections
    k_gemm_yz<<<dim3(13, 2, 2 * BHc), 256, SMEM_GEMM>>>();
    // Z transpose+split
    k_vtrans<<<dim3(49, 8, BHc), dim3(32, 8)>>>();
    // scores + fused stage-1 stats
    k_gemm_sc<<<dim3(13, 13, BHc), 256, SMEM_GEMM>>>();
    k_stats2<<<BHc, 256>>>();
    // single-pass norm + exp (fp16 probs, unnormalized) + row sums
    k_softmax1<<<BHc * Sc, 256>>>();
    // ctx = P @ Z^T (2-term, k-split x2)
    k_gemm_ctx<<<dim3(13, 2, BHc * 2), 256, SMEM_GEMM>>>();
    // final: head-mean, row normalization, straight into d_out
    k_out<<<(Bc * Sc * Cc + 255) / 256, 256>>>(out);
}

// round 7
// speedup vs baseline: 1.4141x; 1.1358x over previous
#include <cuda_runtime.h>
#include <cuda_fp16.h>
#include <cstdint>
#include <math.h>

// ---------------- problem constants ----------------
#define Bc 4
#define Tc 8
#define Cc 256
#define Nc 196
#define Hc 4
#define Sc (Tc * Nc)          // 1568
#define BHc (Bc * Hc)         // 16
#define EPSc 1e-5f
#define NTILE (13 * 13)       // score tiles per bh
#define LOG2E 1.4426950408889634f

typedef __half fp16;

// ---------------- scratch (device globals) ----------------------------------
__device__ fp16  g_Xhi[Bc * Sc * Cc],  g_Xlo[Bc * Sc * Cc];
__device__ fp16  g_Ghi[Hc * Cc * Cc],  g_Glo[Hc * Cc * Cc];   // G_h[a,b]=sum_d Wk[d,a]Wq[d,b]
__device__ fp16  g_Uhi[Hc * Cc * Cc],  g_Ulo[Hc * Cc * Cc];   // U_h[a,b]=sum_d Wo[a,d]Wv[d,b]
__device__ fp16  gYhi[BHc * Sc * Cc],  gYlo[BHc * Sc * Cc];   // Y = X G^T
__device__ float g_Zf32[BHc * Sc * Cc];                        // Z = X U^T
__device__ fp16  gZThi[BHc * Cc * Sc], gZTlo[BHc * Cc * Sc];
__device__ float g_S[(size_t)BHc * Sc * Sc];                   // fp32 scores
__device__ fp16  gP[(size_t)BHc * Sc * Sc];                    // unnormalized probs (fp16)
__device__ float g_CTXH[BHc * Sc * Cc];                        // ctx k-half 0
__device__ float g_CTXH2[BHc * Sc * Cc];                       // ctx k-half 1
__device__ float g_invsum[BHc * Sc];
__device__ float g_part[BHc * NTILE * 2];
__device__ float g_mean[BHc], g_rstd[BHc];

// ---------------- PTX helpers ------------------------------------------------
__device__ __forceinline__ uint32_t cvta_smem(const void* p) {
    uint32_t a;
    asm("{ .reg .u64 t; cvta.to.shared.u64 t, %1; cvt.u32.u64 %0, t; }" : "=r"(a) : "l"(p));
    return a;
}

__device__ __forceinline__ void ldsm_x4(uint32_t& r0, uint32_t& r1, uint32_t& r2,
                                        uint32_t& r3, uint32_t addr) {
    asm volatile("ldmatrix.sync.aligned.m8n8.x4.shared.b16 {%0,%1,%2,%3}, [%4];"
                 : "=r"(r0), "=r"(r1), "=r"(r2), "=r"(r3) : "r"(addr));
}

__device__ __forceinline__ void mma16816(float* d, const uint32_t* a, const uint32_t* b) {
    asm volatile("mma.sync.aligned.m16n8k16.row.col.f32.f16.f16.f32 "
                 "{%0,%1,%2,%3}, {%4,%5,%6,%7}, {%8,%9}, {%0,%1,%2,%3};"
                 : "+f"(d[0]), "+f"(d[1]), "+f"(d[2]), "+f"(d[3])
                 : "r"(a[0]), "r"(a[1]), "r"(a[2]), "r"(a[3]), "r"(b[0]), "r"(b[1]));
}

__device__ __forceinline__ void cp16(uint32_t dst, const void* src, bool v) {
    asm volatile("cp.async.cg.shared.global [%0], [%1], 16, %2;"
                 :: "r"(dst), "l"(src), "r"(v ? 16u : 0u) : "memory");
}

__device__ __forceinline__ void split16(float v, fp16& h, fp16& l) {
    h = __float2half(v);
    l = __float2half(v - __half2float(h));
}

// ---------------- 128x128 fp16-split HMMA GEMM, 3-stage pipeline -------------
// NT form: C[m,n] = alpha * sum_k A[m,k]*B[n,k]; A,B row-major (k contiguous)
// MODE 0: A hi/lo x B hi/lo, 3 terms   (yz)
// MODE 1: A hi/lo x B hi,    2 terms   (scores)
// MODE 2: A single x B hi/lo, 2 terms  (ctx)
#define EPI_F32    0
#define EPI_SCORES 1
#define EPI_SPLIT  2

#define KCH 16
#define ROWB 48                       // 32B data + 16B pad (conflict-free LDSM)
#define ST_ARR (128 * ROWB)           // 6144 B per operand array per stage
#define ST_BYTES (4 * ST_ARR)         // 24576 B per stage
#define SM_ST 128
#define NSTAGE 3
#define SMEM_GEMM (SM_ST + NSTAGE * ST_BYTES)   // 73856

template <int MODE>
static __device__ __forceinline__ void gemm_body(
        const fp16* __restrict__ Ahi, const fp16* __restrict__ Alo,
        const fp16* __restrict__ Bhi, const fp16* __restrict__ Blo,
        int M, int N, int K, int lda, int ldb,
        int m0, int n0, int epi, float alpha,
        float* Cf, fp16* Chi, fp16* Clo, int ldc, float* part) {
    extern __shared__ char smem[];
    float* red = (float*)smem;
    const int tid = threadIdx.x;            // 256 threads, 8 warps
    const int wid = tid >> 5, lane = tid & 31;
    const int wm = (wid >> 1) * 32, wn = (wid & 1) * 64;
    const uint32_t sb = cvta_smem(smem);

    float acc[2][8][4];
#pragma unroll
    for (int i = 0; i < 2; i++)
#pragma unroll
        for (int j = 0; j < 8; j++)
#pragma unroll
            for (int e = 0; e < 4; e++) acc[i][j][e] = 0.f;

    const int nch = K / KCH;
    const int r_ = tid >> 1, u_ = tid & 1;   // per-array cp.async coords

    #define ISSUE(ch)                                                            \
    do {                                                                         \
        const int k0_ = (ch) * KCH;                                              \
        const uint32_t stb_ = sb + SM_ST + ((ch) % NSTAGE) * ST_BYTES;           \
        bool av_ = (m0 + r_) < M;                                                \
        size_t ao_ = av_ ? ((size_t)(m0 + r_) * lda + k0_ + u_ * 8) : 0;         \
        bool bv_ = (n0 + r_) < N;                                                \
        size_t bo_ = bv_ ? ((size_t)(n0 + r_) * ldb + k0_ + u_ * 8) : 0;         \
        uint32_t d_ = stb_ + r_ * ROWB + u_ * 16;                                \
        cp16(d_, Ahi + ao_, av_);                                                \
        if (MODE != 2) cp16(d_ + ST_ARR, Alo + ao_, av_);                        \
        cp16(d_ + 2 * ST_ARR, Bhi + bo_, bv_);                                   \
        if (MODE != 1) cp16(d_ + 3 * ST_ARR, Blo + bo_, bv_);                    \
    } while (0)

    ISSUE(0);
    asm volatile("cp.async.commit_group;" ::: "memory");
    ISSUE(1);
    asm volatile("cp.async.commit_group;" ::: "memory");

    const uint32_t lrow = (uint32_t)(lane & 15);
    const uint32_t lu = (uint32_t)(lane >> 4);

    for (int ch = 0; ch < nch; ch++) {
        if (ch >= nch - 1) {
            asm volatile("cp.async.wait_group 0;" ::: "memory");
        } else {
            asm volatile("cp.async.wait_group 1;" ::: "memory");
        }
        __syncthreads();
        if (ch + 2 < nch) {
            ISSUE(ch + 2);
            asm volatile("cp.async.commit_group;" ::: "memory");
        }

        const uint32_t stb = sb + SM_ST + (ch % NSTAGE) * ST_BYTES;
        uint32_t af[2][4];     // A hi [0], A lo [1] (MODE2 uses [0] only)
        uint32_t bfr[8][2];

        // A fragments
        {
            uint32_t a0 = stb + (wm + lrow) * ROWB + lu * 16;
            uint32_t a1 = stb + (wm + 16 + lrow) * ROWB + lu * 16;
            ldsm_x4(af[0][0], af[0][1], af[0][2], af[0][3], (lrow < 16 ? a0 : a0)); // af[0]: rows wm..wm+15? no:
            // af layout: af[t] covers m rows [wm + t*16, wm + t*16 + 16)
            (void)a1;
        }
        // NOTE: need two m16 tiles; load explicitly:
        uint32_t afm[2][2][4];   // [hi/lo][im][regs]
#pragma unroll
        for (int im = 0; im < 2; im++) {
            uint32_t addr = stb + (wm + im * 16 + lrow) * ROWB + lu * 16;
            ldsm_x4(afm[0][im][0], afm[0][im][1], afm[0][im][2], afm[0][im][3], addr);
        }
        if (MODE != 2) {
#pragma unroll
            for (int im = 0; im < 2; im++) {
                uint32_t addr = stb + ST_ARR + (wm + im * 16 + lrow) * ROWB + lu * 16;
                ldsm_x4(afm[1][im][0], afm[1][im][1], afm[1][im][2], afm[1][im][3], addr);
            }
        }
        // B hi fragments
#pragma unroll
        for (int inn = 0; inn < 4; inn++) {
            uint32_t addr = stb + 2 * ST_ARR + (wn + inn * 16 + lrow) * ROWB + lu * 16;
            uint32_t r0, r1, r2, r3;
            ldsm_x4(r0, r1, r2, r3, addr);
            bfr[inn * 2 + 0][0] = r0; bfr[inn * 2 + 0][1] = r2;
            bfr[inn * 2 + 1][0] = r1; bfr[inn * 2 + 1][1] = r3;
        }
        // terms with B hi
#pragma unroll
        for (int im = 0; im < 2; im++)
#pragma unroll
            for (int jn = 0; jn < 8; jn++) mma16816(acc[im][jn], afm[0][im], bfr[jn]);
        if (MODE != 2) {
#pragma unroll
            for (int im = 0; im < 2; im++)
#pragma unroll
                for (int jn = 0; jn < 8; jn++) mma16816(acc[im][jn], afm[1][im], bfr[jn]);
        }
        // term with B lo
        if (MODE != 1) {
#pragma unroll
            for (int inn = 0; inn < 4; inn++) {
                uint32_t addr = stb + 3 * ST_ARR + (wn + inn * 16 + lrow) * ROWB + lu * 16;
                uint32_t r0, r1, r2, r3;
                ldsm_x4(r0, r1, r2, r3, addr);
                bfr[inn * 2 + 0][0] = r0; bfr[inn * 2 + 0][1] = r2;
                bfr[inn * 2 + 1][0] = r1; bfr[inn * 2 + 1][1] = r3;
            }
#pragma unroll
            for (int im = 0; im < 2; im++)
#pragma unroll
                for (int jn = 0; jn < 8; jn++) mma16816(acc[im][jn], afm[0][im], bfr[jn]);
        }
    }
    #undef ISSUE

    // ---------------- epilogue ----------------
    float psum = 0.f, psq = 0.f;
#pragma unroll
    for (int im = 0; im < 2; im++) {
#pragma unroll
        for (int jn = 0; jn < 8; jn++) {
            int r0 = m0 + wm + im * 16 + (lane >> 2);
            int cn = n0 + wn + jn * 8 + (lane & 3) * 2;
            bool cv = cn < N;
            float v0 = acc[im][jn][0] * alpha, v1 = acc[im][jn][1] * alpha;
            float v2 = acc[im][jn][2] * alpha, v3 = acc[im][jn][3] * alpha;
            if (epi == EPI_SPLIT) {
                if (cv && r0 < M) {
                    __half2 hh, ll;
                    split16(v0, hh.x, ll.x); split16(v1, hh.y, ll.y);
                    *(__half2*)&Chi[(size_t)r0 * ldc + cn] = hh;
                    *(__half2*)&Clo[(size_t)r0 * ldc + cn] = ll;
                }
                if (cv && r0 + 8 < M) {
                    __half2 hh, ll;
                    split16(v2, hh.x, ll.x); split16(v3, hh.y, ll.y);
                    *(__half2*)&Chi[(size_t)(r0 + 8) * ldc + cn] = hh;
                    *(__half2*)&Clo[(size_t)(r0 + 8) * ldc + cn] = ll;
                }
            } else {
                if (cv && r0 < M) {
                    *(float2*)&Cf[(size_t)r0 * ldc + cn] = make_float2(v0, v1);
                    psum += v0 + v1; psq += v0 * v0 + v1 * v1;
                }
                if (cv && r0 + 8 < M) {
                    *(float2*)&Cf[(size_t)(r0 + 8) * ldc + cn] = make_float2(v2, v3);
                    psum += v2 + v3; psq += v2 * v2 + v3 * v3;
                }
            }
        }
    }
    if (epi == EPI_SCORES) {
#pragma unroll
        for (int o = 16; o; o >>= 1) {
            psum += __shfl_xor_sync(0xffffffffu, psum, o);
            psq  += __shfl_xor_sync(0xffffffffu, psq,  o);
        }
        if (lane == 0) { red[wid] = psum; red[8 + wid] = psq; }
        __syncthreads();
        if (tid == 0) {
            float s = 0.f, q = 0.f;
#pragma unroll
            for (int w = 0; w < 8; w++) { s += red[w]; q += red[8 + w]; }
            part[0] = s;
            part[1] = q;
        }
    }
}

// ---------------- GEMM wrappers ----------------------------------------------
// Y_h = X_b G_h^T (split epi), Z_h = X_b U_h^T (f32 epi)
__global__ __launch_bounds__(256, 2) void k_gemm_yz() {
    int z = blockIdx.z;
    int bh = z >> 1, which = z & 1;
    int b = bh / Hc, h = bh % Hc;
    const fp16* Ah = g_Xhi + (size_t)b * Sc * Cc;
    const fp16* Al = g_Xlo + (size_t)b * Sc * Cc;
    int m0 = blockIdx.x * 128, n0 = blockIdx.y * 128;
    if (which == 0) {
        gemm_body<0>(Ah, Al, g_Ghi + (size_t)h * Cc * Cc, g_Glo + (size_t)h * Cc * Cc,
                     Sc, Cc, Cc, Cc, Cc, m0, n0, EPI_SPLIT, 1.f,
                     nullptr, gYhi + (size_t)bh * Sc * Cc, gYlo + (size_t)bh * Sc * Cc,
                     Cc, nullptr);
    } else {
        gemm_body<0>(Ah, Al, g_Uhi + (size_t)h * Cc * Cc, g_Ulo + (size_t)h * Cc * Cc,
                     Sc, Cc, Cc, Cc, Cc, m0, n0, EPI_F32, 1.f,
                     g_Zf32 + (size_t)bh * Sc * Cc, nullptr, nullptr, Cc, nullptr);
    }
}

// scores = Y X^T / sqrt(S), 2-term (X hi only), + fused stage-1 stats
__global__ __launch_bounds__(256, 2) void k_gemm_sc() {
    int bh = blockIdx.z;
    int b = bh / Hc;
    int m0 = blockIdx.x * 128, n0 = blockIdx.y * 128;
    float alpha = rsqrtf((float)Sc);
    gemm_body<1>(gYhi + (size_t)bh * Sc * Cc, gYlo + (size_t)bh * Sc * Cc,
                 g_Xhi + (size_t)b * Sc * Cc, nullptr,
                 Sc, Sc, Cc, Cc, Cc, m0, n0, EPI_SCORES, alpha,
                 g_S + (size_t)bh * Sc * Sc, nullptr, nullptr, Sc,
                 &g_part[((size_t)bh * NTILE + blockIdx.y * 13 + blockIdx.x) * 2]);
}

// ctx = P (fp16, single) @ Z^T (hi/lo), K-split into [0,768) and [768,1568)
__global__ __launch_bounds__(256, 2) void k_gemm_ctx() {
    int z = blockIdx.z;
    int bh = z >> 1, half = z & 1;
    int koff = half ? 768 : 0;
    int klen = half ? (Sc - 768) : 768;
    int m0 = blockIdx.x * 128, n0 = blockIdx.y * 128;
    float* outbuf = (half ? g_CTXH2 : g_CTXH) + (size_t)bh * Sc * Cc;
    gemm_body<2>(gP + (size_t)bh * Sc * Sc + koff, nullptr,
                 gZThi + (size_t)bh * Cc * Sc + koff, gZTlo + (size_t)bh * Cc * Sc + koff,
                 Sc, Cc, klen, Sc, Sc, m0, n0, EPI_F32, 1.f,
                 outbuf, nullptr, nullptr, Cc, nullptr);
}

// ---------------- small fp32 weight-product kernels ---------------------------
// G_h[a,b] = sum_d Wk_h[d,a] * Wq_h[d,b]
__global__ __launch_bounds__(256) void k_gmat(const float* __restrict__ Wq,
                                              const float* __restrict__ Wk) {
    int h = blockIdx.z;
    int a0 = blockIdx.x * 16, b0 = blockIdx.y * 16;
    int tx = threadIdx.x & 15, ty = threadIdx.x >> 4;
    __shared__ float A[16][17], B[16][17];
    const float* wk = Wk + (size_t)h * Cc * Cc;
    const float* wq = Wq + (size_t)h * Cc * Cc;
    float acc = 0.f;
    for (int d0 = 0; d0 < Cc; d0 += 16) {
        A[ty][tx] = wk[(d0 + ty) * Cc + a0 + tx];
        B[ty][tx] = wq[(d0 + ty) * Cc + b0 + tx];
        __syncthreads();
#pragma unroll
        for (int dd = 0; dd < 16; dd++) acc += A[dd][ty] * B[dd][tx];
        __syncthreads();
    }
    size_t o = (size_t)h * Cc * Cc + (a0 + ty) * Cc + b0 + tx;
    split16(acc, g_Ghi[o], g_Glo[o]);
}

// U_h[a,b] = sum_d Wo[a,d] * Wv_h[d,b]
__global__ __launch_bounds__(256) void k_umat(const float* __restrict__ Wv,
                                              const float* __restrict__ Wo) {
    int h = blockIdx.z;
    int a0 = blockIdx.x * 16, b0 = blockIdx.y * 16;
    int tx = threadIdx.x & 15, ty = threadIdx.x >> 4;
    __shared__ float A[16][17], B[16][17];
    const float* wv = Wv + (size_t)h * Cc * Cc;
    float acc = 0.f;
    for (int d0 = 0; d0 < Cc; d0 += 16) {
        A[ty][tx] = Wo[(a0 + ty) * Cc + d0 + tx];
        B[ty][tx] = wv[(d0 + ty) * Cc + b0 + tx];
        __syncthreads();
#pragma unroll
        for (int dd = 0; dd < 16; dd++) acc += A[ty][dd] * B[dd][tx];
        __syncthreads();
    }
    size_t o = (size_t)h * Cc * Cc + (a0 + ty) * Cc + b0 + tx;
    split16(acc, g_Uhi[o], g_Ulo[o]);
}

// ---------------- elementwise / reshape kernels -------------------------------
__global__ void k_transpose(const float* __restrict__ emb) {
    __shared__ float tile[32][33];
    int bt = blockIdx.z;
    int n0 = blockIdx.x * 32, c0 = blockIdx.y * 32;
    int x = threadIdx.x, y = threadIdx.y;
    const float* src = emb + (size_t)bt * Cc * Nc;
    fp16* dh = g_Xhi + (size_t)bt * Nc * Cc;
    fp16* dl = g_Xlo + (size_t)bt * Nc * Cc;
#pragma unroll
    for (int i = 0; i < 32; i += 8) {
        int c = c0 + y + i, n = n0 + x;
        tile[y + i][x] = (n < Nc) ? src[c * Nc + n] : 0.f;
    }
    __syncthreads();
#pragma unroll
    for (int i = 0; i < 32; i += 8) {
        int n = n0 + y + i, c = c0 + x;
        if (n < Nc) {
            float v = tile[x][y + i];
            split16(v, dh[n * Cc + c], dl[n * Cc + c]);
        }
    }
}

// Z [bh][S][C] fp32 -> ZT [bh][C][S] fp16 hi/lo
__global__ void k_vtrans() {
    __shared__ float t[32][33];
    int bh = blockIdx.z;
    int s0 = blockIdx.x * 32, c0 = blockIdx.y * 32;
    int x = threadIdx.x, y = threadIdx.y;
    const float* Z = g_Zf32 + (size_t)bh * Sc * Cc;
    fp16* th = gZThi + (size_t)bh * Cc * Sc;
    fp16* tl = gZTlo + (size_t)bh * Cc * Sc;
#pragma unroll
    for (int i = 0; i < 32; i += 8)
        t[y + i][x] = Z[(size_t)(s0 + y + i) * Cc + c0 + x];
    __syncthreads();
#pragma unroll
    for (int i = 0; i < 32; i += 8) {
        float v = t[x][y + i];
        size_t o = (size_t)(c0 + y + i) * Sc + s0 + x;
        split16(v, th[o], tl[o]);
    }
}

__global__ __launch_bounds__(256) void k_stats2() {
    int bh = blockIdx.x;
    float s = 0.f, q = 0.f;
    for (int i = threadIdx.x; i < NTILE; i += 256) {
        s += g_part[((size_t)bh * NTILE + i) * 2 + 0];
        q += g_part[((size_t)bh * NTILE + i) * 2 + 1];
    }
    __shared__ float ss[256], sq[256];
    int tid = threadIdx.x;
    ss[tid] = s; sq[tid] = q;
    __syncthreads();
    for (int st = 128; st > 0; st >>= 1) {
        if (tid < st) { ss[tid] += ss[tid + st]; sq[tid] += sq[tid + st]; }
        __syncthreads();
    }
    if (tid == 0) {
        float cnt = (float)Sc * (float)Sc;
        float mean = ss[0] / cnt;
        float var = sq[0] / cnt - mean * mean;
        g_mean[bh] = mean;
        g_rstd[bh] = rsqrtf(var + EPSc);
    }
}

// single-pass: p = exp(normed score) in fp16 (unnormalized), row sums -> invsum
__global__ __launch_bounds__(256) void k_softmax1() {
    int row = blockIdx.x;                 // 0..BHc*Sc-1
    int bh = row / Sc;
    size_t base = (size_t)row * Sc;
    float aa = g_rstd[bh] * LOG2E;
    float bb = -g_mean[bh] * g_rstd[bh] * LOG2E;
    const float2* src = (const float2*)(g_S + base);
    uint32_t* dst = (uint32_t*)(gP + base);
    float lsum = 0.f;
    for (int pi = threadIdx.x; pi < Sc / 2; pi += 256) {
        float2 s = src[pi];
        float z0 = fmaf(s.x, aa, bb);
        float z1 = fmaf(s.y, aa, bb);
        __half2 zh = __floats2half2_rn(z0, z1);
        uint32_t zi = *reinterpret_cast<uint32_t*>(&zh);
        uint32_t ei;
        asm("ex2.approx.f16x2 %0, %1;" : "=r"(ei) : "r"(zi));
        dst[pi] = ei;
        __half2 eh = *reinterpret_cast<__half2*>(&ei);
        float2 ef = __half22float2(eh);
        lsum += ef.x + ef.y;
    }
    __shared__ float red[256];
    int tid = threadIdx.x;
    red[tid] = lsum;
    __syncthreads();
    for (int st = 128; st > 0; st >>= 1) {
        if (tid < st) red[tid] += red[tid + st];
        __syncthreads();
    }
    if (tid == 0) g_invsum[row] = 1.f / red[0];
}

// out[b,s,d] = (1/H) sum_h invsum[bh,s] * (ctx1+ctx2)[bh,s,d]
__global__ __launch_bounds__(256) void k_out(float* __restrict__ out) {
    int idx = blockIdx.x * 256 + threadIdx.x;
    if (idx >= Bc * Sc * Cc) return;
    int b = idx / (Sc * Cc);
    int rem = idx % (Sc * Cc);
    int s = rem / Cc;
    float v = 0.f;
#pragma unroll
    for (int h = 0; h < Hc; h++) {
        int bh = b * Hc + h;
        size_t o = ((size_t)bh * Sc * Cc) + rem;
        v += (g_CTXH[o] + g_CTXH2[o]) * g_invsum[(size_t)bh * Sc + s];
    }
    out[idx] = 0.25f * v;
}

// ---------------- launch -------------------------------------------------------
extern "C" void kernel_launch(void* const* d_in, const int* in_sizes, int n_in,
                              void* d_out, int out_size) {
    const float* emb = (const float*)d_in[0];
    const float* Wq  = (const float*)d_in[1];
    const float* Wk  = (const float*)d_in[2];
    const float* Wv  = (const float*)d_in[3];
    const float* Wo  = (const float*)d_in[4];
    float* out = (float*)d_out;

    static bool attr_done = false;
    if (!attr_done) {
        cudaFuncSetAttribute(k_gemm_yz,  cudaFuncAttributeMaxDynamicSharedMemorySize, SMEM_GEMM);
        cudaFuncSetAttribute(k_gemm_sc,  cudaFuncAttributeMaxDynamicSharedMemorySize, SMEM_GEMM);
        cudaFuncSetAttribute(k_gemm_ctx, cudaFuncAttributeMaxDynamicSharedMemorySize, SMEM_GEMM);
        attr_done = true;
    }

    // input prep
    k_transpose<<<dim3(7, 8, Bc * Tc), dim3(32, 8)>>>(emb);
    k_gmat<<<dim3(16, 16, Hc), 256>>>(Wq, Wk);
    k_umat<<<dim3(16, 16, Hc), 256>>>(Wv, Wo);

    // Y and Z projections
    k_gemm_yz<<<dim3(13, 2, 2 * BHc), 256, SMEM_GEMM>>>();
    // Z transpose+split
    k_vtrans<<<dim3(49, 8, BHc), dim3(32, 8)>>>();
    // scores + fused stage-1 stats (2-term)
    k_gemm_sc<<<dim3(13, 13, BHc), 256, SMEM_GEMM>>>();
    k_stats2<<<BHc, 256>>>();
    // single-pass norm + exp (fp16 probs, unnormalized) + row sums
    k_softmax1<<<BHc * Sc, 256>>>();
    // ctx = P @ Z^T (2-term, k-split x2)
    k_gemm_ctx<<<dim3(13, 2, BHc * 2), 256, SMEM_GEMM>>>();
    // final: head-mean, row normalization, straight into d_out
    k_out<<<(Bc * Sc * Cc + 255) / 256, 256>>>(out);
}

// round 8
// speedup vs baseline: 1.5314x; 1.0830x over previous
#include <cuda_runtime.h>
#include <cuda_fp16.h>
#include <cstdint>
#include <math.h>

// ---------------- problem constants ----------------
#define Bc 4
#define Tc 8
#define Cc 256
#define Nc 196
#define Hc 4
#define Sc (Tc * Nc)          // 1568
#define BHc (Bc * Hc)         // 16
#define EPSc 1e-5f
#define NTILE (13 * 7)        // score tiles per bh (m13 x n7)
#define LOG2E 1.4426950408889634f

typedef __half fp16;

// ---------------- scratch (device globals) ----------------------------------
__device__ fp16  g_Xhi[Bc * Sc * Cc],  g_Xlo[Bc * Sc * Cc];
__device__ fp16  g_Ghi[Hc * Cc * Cc],  g_Glo[Hc * Cc * Cc];   // G_h = Wk^T Wq
__device__ fp16  g_Uhi[Hc * Cc * Cc],  g_Ulo[Hc * Cc * Cc];   // U_h = Wo Wv
__device__ fp16  gYhi[BHc * Sc * Cc],  gYlo[BHc * Sc * Cc];   // Y = X G^T
__device__ float g_Zf32[BHc * Sc * Cc];                        // Z = X U^T
__device__ fp16  gZT[BHc * Cc * Sc];                           // Z^T single fp16
__device__ float g_S[(size_t)BHc * Sc * Sc];                   // fp32 scores
__device__ fp16  gP[(size_t)BHc * Sc * Sc];                    // unnormalized probs
__device__ float g_CTXH[BHc * Sc * Cc];                        // ctx k-half 0
__device__ float g_CTXH2[BHc * Sc * Cc];                       // ctx k-half 1
__device__ float g_invsum[BHc * Sc];
__device__ float g_part[BHc * NTILE * 2];
__device__ float g_mean[BHc], g_rstd[BHc];

// ---------------- PTX helpers ------------------------------------------------
__device__ __forceinline__ uint32_t cvta_smem(const void* p) {
    uint32_t a;
    asm("{ .reg .u64 t; cvta.to.shared.u64 t, %1; cvt.u32.u64 %0, t; }" : "=r"(a) : "l"(p));
    return a;
}

__device__ __forceinline__ void ldsm_x4(uint32_t& r0, uint32_t& r1, uint32_t& r2,
                                        uint32_t& r3, uint32_t addr) {
    asm volatile("ldmatrix.sync.aligned.m8n8.x4.shared.b16 {%0,%1,%2,%3}, [%4];"
                 : "=r"(r0), "=r"(r1), "=r"(r2), "=r"(r3) : "r"(addr));
}

__device__ __forceinline__ void mma16816(float* d, const uint32_t* a, const uint32_t* b) {
    asm volatile("mma.sync.aligned.m16n8k16.row.col.f32.f16.f16.f32 "
                 "{%0,%1,%2,%3}, {%4,%5,%6,%7}, {%8,%9}, {%0,%1,%2,%3};"
                 : "+f"(d[0]), "+f"(d[1]), "+f"(d[2]), "+f"(d[3])
                 : "r"(a[0]), "r"(a[1]), "r"(a[2]), "r"(a[3]), "r"(b[0]), "r"(b[1]));
}

__device__ __forceinline__ void cp16(uint32_t dst, const void* src, bool v) {
    asm volatile("cp.async.cg.shared.global [%0], [%1], 16, %2;"
                 :: "r"(dst), "l"(src), "r"(v ? 16u : 0u) : "memory");
}

__device__ __forceinline__ void split16(float v, fp16& h, fp16& l) {
    h = __float2half(v);
    l = __float2half(v - __half2float(h));
}

// ---------------- 128x256 fp16-split HMMA GEMM, 3-stage, 64x64 warp tiles ----
// NT form: C[m,n] = alpha * sum_k A[m,k]*B[n,k]; A,B row-major (k contiguous)
// NA=2: A hi/lo (terms Ahi*Bhi + Alo*Bhi); NB=2 adds Ahi*Blo.
#define EPI_F32    0
#define EPI_SCORES 1
#define EPI_SPLIT  2

#define KCH 32
#define ROWB 80                       // 64B data + 16B pad (conflict-free LDSM)
#define OF_A0 0
#define OF_A1 10240                   // 128 rows * 80
#define OF_B0 20480
#define OF_B1 40960                   // 256 rows * 80
#define ST_BYTES 61440
#define SM_ST 128
#define NSTAGE 3
#define SMEM_GEMM (SM_ST + NSTAGE * ST_BYTES)   // 184448

template <int NA, int NB>
static __device__ __forceinline__ void gemm_body(
        const fp16* __restrict__ Ahi, const fp16* __restrict__ Alo,
        const fp16* __restrict__ Bhi, const fp16* __restrict__ Blo,
        int M, int N, int K, int lda, int ldb,
        int m0, int n0, int epi, float alpha,
        float* Cf, fp16* Chi, fp16* Clo, int ldc, float* part) {
    extern __shared__ char smem[];
    float* red = (float*)smem;
    const int tid = threadIdx.x;            // 256 threads, 8 warps (2m x 4n)
    const int wid = tid >> 5, lane = tid & 31;
    const int wm = (wid >> 2) * 64, wn = (wid & 3) * 64;
    const uint32_t sb = cvta_smem(smem);

    float acc[4][8][4];
#pragma unroll
    for (int i = 0; i < 4; i++)
#pragma unroll
        for (int j = 0; j < 8; j++)
#pragma unroll
            for (int e = 0; e < 4; e++) acc[i][j][e] = 0.f;

    const int nch = K / KCH;

    #define ISSUE(ch)                                                            \
    do {                                                                         \
        const int k0_ = (ch) * KCH;                                              \
        const uint32_t stb_ = sb + SM_ST + ((ch) % NSTAGE) * ST_BYTES;           \
        _Pragma("unroll")                                                        \
        for (int l = 0; l < 2; l++) {          /* A: 128 rows x 4 units */       \
            int it = tid + l * 256;                                              \
            int r = it >> 2, u = it & 3;                                         \
            bool av = (m0 + r) < M;                                              \
            size_t ao = av ? ((size_t)(m0 + r) * lda + k0_ + u * 8) : 0;         \
            uint32_t d = stb_ + OF_A0 + r * ROWB + u * 16;                       \
            cp16(d, Ahi + ao, av);                                               \
            if (NA == 2) cp16(d + OF_A1, Alo + ao, av);                          \
        }                                                                        \
        _Pragma("unroll")                                                        \
        for (int l = 0; l < 4; l++) {          /* B: 256 rows x 4 units */       \
            int it = tid + l * 256;                                              \
            int r = it >> 2, u = it & 3;                                         \
            bool bv = (n0 + r) < N;                                              \
            size_t bo = bv ? ((size_t)(n0 + r) * ldb + k0_ + u * 8) : 0;         \
            uint32_t d = stb_ + OF_B0 + r * ROWB + u * 16;                       \
            cp16(d, Bhi + bo, bv);                                               \
            if (NB == 2) cp16(d + (OF_B1 - OF_B0), Blo + bo, bv);                \
        }                                                                        \
    } while (0)

    ISSUE(0);
    asm volatile("cp.async.commit_group;" ::: "memory");
    if (nch > 1) ISSUE(1);
    asm volatile("cp.async.commit_group;" ::: "memory");

    const uint32_t lrow = (uint32_t)(lane & 15);
    const uint32_t lu = (uint32_t)(lane >> 4);

    for (int ch = 0; ch < nch; ch++) {
        if (ch < nch - 1) {
            asm volatile("cp.async.wait_group 1;" ::: "memory");
        } else {
            asm volatile("cp.async.wait_group 0;" ::: "memory");
        }
        __syncthreads();
        if (ch + 2 < nch) {
            ISSUE(ch + 2);
            asm volatile("cp.async.commit_group;" ::: "memory");
        }

        const uint32_t stb = sb + SM_ST + (ch % NSTAGE) * ST_BYTES;
#pragma unroll
        for (int ku = 0; ku < 2; ku++) {
            const uint32_t koffb = ku * 32 + lu * 16;
            uint32_t af[4][4];
            uint32_t bfr[8][2];

            // A-hi frags (4 m16 tiles)
#pragma unroll
            for (int im = 0; im < 4; im++) {
                uint32_t addr = stb + OF_A0 + (wm + im * 16 + lrow) * ROWB + koffb;
                ldsm_x4(af[im][0], af[im][1], af[im][2], af[im][3], addr);
            }
            // B-hi frags (4 n16 tiles -> 8 n8 frags)
#pragma unroll
            for (int inn = 0; inn < 4; inn++) {
                uint32_t addr = stb + OF_B0 + (wn + inn * 16 + lrow) * ROWB + koffb;
                uint32_t r0, r1, r2, r3;
                ldsm_x4(r0, r1, r2, r3, addr);
                bfr[inn * 2 + 0][0] = r0; bfr[inn * 2 + 0][1] = r2;
                bfr[inn * 2 + 1][0] = r1; bfr[inn * 2 + 1][1] = r3;
            }
            // term: Ahi x Bhi
#pragma unroll
            for (int im = 0; im < 4; im++)
#pragma unroll
                for (int jn = 0; jn < 8; jn++) mma16816(acc[im][jn], af[im], bfr[jn]);

            if (NA == 2) {
                // term: Alo x Bhi
#pragma unroll
                for (int im = 0; im < 4; im++) {
                    uint32_t addr = stb + OF_A1 + (wm + im * 16 + lrow) * ROWB + koffb;
                    ldsm_x4(af[im][0], af[im][1], af[im][2], af[im][3], addr);
                }
#pragma unroll
                for (int im = 0; im < 4; im++)
#pragma unroll
                    for (int jn = 0; jn < 8; jn++) mma16816(acc[im][jn], af[im], bfr[jn]);
            }
            if (NB == 2) {
                // reload Ahi, load Blo; term: Ahi x Blo
#pragma unroll
                for (int im = 0; im < 4; im++) {
                    uint32_t addr = stb + OF_A0 + (wm + im * 16 + lrow) * ROWB + koffb;
                    ldsm_x4(af[im][0], af[im][1], af[im][2], af[im][3], addr);
                }
#pragma unroll
                for (int inn = 0; inn < 4; inn++) {
                    uint32_t addr = stb + OF_B1 + (wn + inn * 16 + lrow) * ROWB + koffb;
                    uint32_t r0, r1, r2, r3;
                    ldsm_x4(r0, r1, r2, r3, addr);
                    bfr[inn * 2 + 0][0] = r0; bfr[inn * 2 + 0][1] = r2;
                    bfr[inn * 2 + 1][0] = r1; bfr[inn * 2 + 1][1] = r3;
                }
#pragma unroll
                for (int im = 0; im < 4; im++)
#pragma unroll
                    for (int jn = 0; jn < 8; jn++) mma16816(acc[im][jn], af[im], bfr[jn]);
            }
        }
    }
    #undef ISSUE

    // ---------------- epilogue ----------------
    float psum = 0.f, psq = 0.f;
#pragma unroll
    for (int im = 0; im < 4; im++) {
#pragma unroll
        for (int jn = 0; jn < 8; jn++) {
            int r0 = m0 + wm + im * 16 + (lane >> 2);
            int cn = n0 + wn + jn * 8 + (lane & 3) * 2;
            bool cv = cn < N;
            float v0 = acc[im][jn][0] * alpha, v1 = acc[im][jn][1] * alpha;
            float v2 = acc[im][jn][2] * alpha, v3 = acc[im][jn][3] * alpha;
            if (epi == EPI_SPLIT) {
                if (cv && r0 < M) {
                    __half2 hh, ll;
                    split16(v0, hh.x, ll.x); split16(v1, hh.y, ll.y);
                    *(__half2*)&Chi[(size_t)r0 * ldc + cn] = hh;
                    *(__half2*)&Clo[(size_t)r0 * ldc + cn] = ll;
                }
                if (cv && r0 + 8 < M) {
                    __half2 hh, ll;
                    split16(v2, hh.x, ll.x); split16(v3, hh.y, ll.y);
                    *(__half2*)&Chi[(size_t)(r0 + 8) * ldc + cn] = hh;
                    *(__half2*)&Clo[(size_t)(r0 + 8) * ldc + cn] = ll;
                }
            } else {
                if (cv && r0 < M) {
                    *(float2*)&Cf[(size_t)r0 * ldc + cn] = make_float2(v0, v1);
                    psum += v0 + v1; psq += v0 * v0 + v1 * v1;
                }
                if (cv && r0 + 8 < M) {
                    *(float2*)&Cf[(size_t)(r0 + 8) * ldc + cn] = make_float2(v2, v3);
                    psum += v2 + v3; psq += v2 * v2 + v3 * v3;
                }
            }
        }
    }
    if (epi == EPI_SCORES) {
#pragma unroll
        for (int o = 16; o; o >>= 1) {
            psum += __shfl_xor_sync(0xffffffffu, psum, o);
            psq  += __shfl_xor_sync(0xffffffffu, psq,  o);
        }
        if (lane == 0) { red[wid] = psum; red[8 + wid] = psq; }
        __syncthreads();
        if (tid == 0) {
            float s = 0.f, q = 0.f;
#pragma unroll
            for (int w = 0; w < 8; w++) { s += red[w]; q += red[8 + w]; }
            part[0] = s;
            part[1] = q;
        }
    }
}

// ---------------- GEMM wrappers ----------------------------------------------
// Y_h = X_b G_h^T (split epi), Z_h = X_b U_h^T (f32 epi); N=256 single n-tile
__global__ __launch_bounds__(256) void k_gemm_yz() {
    int z = blockIdx.z;
    int bh = z >> 1, which = z & 1;
    int b = bh / Hc, h = bh % Hc;
    const fp16* Ah = g_Xhi + (size_t)b * Sc * Cc;
    const fp16* Al = g_Xlo + (size_t)b * Sc * Cc;
    int m0 = blockIdx.x * 128;
    if (which == 0) {
        gemm_body<2, 2>(Ah, Al, g_Ghi + (size_t)h * Cc * Cc, g_Glo + (size_t)h * Cc * Cc,
                        Sc, Cc, Cc, Cc, Cc, m0, 0, EPI_SPLIT, 1.f,
                        nullptr, gYhi + (size_t)bh * Sc * Cc, gYlo + (size_t)bh * Sc * Cc,
                        Cc, nullptr);
    } else {
        gemm_body<2, 2>(Ah, Al, g_Uhi + (size_t)h * Cc * Cc, g_Ulo + (size_t)h * Cc * Cc,
                        Sc, Cc, Cc, Cc, Cc, m0, 0, EPI_F32, 1.f,
                        g_Zf32 + (size_t)bh * Sc * Cc, nullptr, nullptr, Cc, nullptr);
    }
}

// scores = Y X^T / sqrt(S), 2-term (X hi only), fused stage-1 stats
__global__ __launch_bounds__(256) void k_gemm_sc() {
    int bh = blockIdx.z;
    int b = bh / Hc;
    int m0 = blockIdx.x * 128, n0 = blockIdx.y * 256;
    float alpha = rsqrtf((float)Sc);
    gemm_body<2, 1>(gYhi + (size_t)bh * Sc * Cc, gYlo + (size_t)bh * Sc * Cc,
                    g_Xhi + (size_t)b * Sc * Cc, nullptr,
                    Sc, Sc, Cc, Cc, Cc, m0, n0, EPI_SCORES, alpha,
                    g_S + (size_t)bh * Sc * Sc, nullptr, nullptr, Sc,
                    &g_part[((size_t)bh * NTILE + blockIdx.y * 13 + blockIdx.x) * 2]);
}

// ctx = P (fp16) @ Z^T (fp16), 1-term, K-split [0,768) / [768,1568)
__global__ __launch_bounds__(256) void k_gemm_ctx() {
    int z = blockIdx.z;
    int bh = z >> 1, half = z & 1;
    int koff = half ? 768 : 0;
    int klen = half ? (Sc - 768) : 768;
    int m0 = blockIdx.x * 128;
    float* outbuf = (half ? g_CTXH2 : g_CTXH) + (size_t)bh * Sc * Cc;
    gemm_body<1, 1>(gP + (size_t)bh * Sc * Sc + koff, nullptr,
                    gZT + (size_t)bh * Cc * Sc + koff, nullptr,
                    Sc, Cc, klen, Sc, Sc, m0, 0, EPI_F32, 1.f,
                    outbuf, nullptr, nullptr, Cc, nullptr);
}

// ---------------- small fp32 weight-product kernels ---------------------------
__global__ __launch_bounds__(256) void k_gmat(const float* __restrict__ Wq,
                                              const float* __restrict__ Wk) {
    int h = blockIdx.z;
    int a0 = blockIdx.x * 16, b0 = blockIdx.y * 16;
    int tx = threadIdx.x & 15, ty = threadIdx.x >> 4;
    __shared__ float A[16][17], B[16][17];
    const float* wk = Wk + (size_t)h * Cc * Cc;
    const float* wq = Wq + (size_t)h * Cc * Cc;
    float acc = 0.f;
    for (int d0 = 0; d0 < Cc; d0 += 16) {
        A[ty][tx] = wk[(d0 + ty) * Cc + a0 + tx];
        B[ty][tx] = wq[(d0 + ty) * Cc + b0 + tx];
        __syncthreads();
#pragma unroll
        for (int dd = 0; dd < 16; dd++) acc += A[dd][ty] * B[dd][tx];
        __syncthreads();
    }
    size_t o = (size_t)h * Cc * Cc + (a0 + ty) * Cc + b0 + tx;
    split16(acc, g_Ghi[o], g_Glo[o]);
}

__global__ __launch_bounds__(256) void k_umat(const float* __restrict__ Wv,
                                              const float* __restrict__ Wo) {
    int h = blockIdx.z;
    int a0 = blockIdx.x * 16, b0 = blockIdx.y * 16;
    int tx = threadIdx.x & 15, ty = threadIdx.x >> 4;
    __shared__ float A[16][17], B[16][17];
    const float* wv = Wv + (size_t)h * Cc * Cc;
    float acc = 0.f;
    for (int d0 = 0; d0 < Cc; d0 += 16) {
        A[ty][tx] = Wo[(a0 + ty) * Cc + d0 + tx];
        B[ty][tx] = wv[(d0 + ty) * Cc + b0 + tx];
        __syncthreads();
#pragma unroll
        for (int dd = 0; dd < 16; dd++) acc += A[ty][dd] * B[dd][tx];
        __syncthreads();
    }
    size_t o = (size_t)h * Cc * Cc + (a0 + ty) * Cc + b0 + tx;
    split16(acc, g_Uhi[o], g_Ulo[o]);
}

// ---------------- elementwise / reshape kernels -------------------------------
__global__ void k_transpose(const float* __restrict__ emb) {
    __shared__ float tile[32][33];
    int bt = blockIdx.z;
    int n0 = blockIdx.x * 32, c0 = blockIdx.y * 32;
    int x = threadIdx.x, y = threadIdx.y;
    const float* src = emb + (size_t)bt * Cc * Nc;
    fp16* dh = g_Xhi + (size_t)bt * Nc * Cc;
    fp16* dl = g_Xlo + (size_t)bt * Nc * Cc;
#pragma unroll
    for (int i = 0; i < 32; i += 8) {
        int c = c0 + y + i, n = n0 + x;
        tile[y + i][x] = (n < Nc) ? src[c * Nc + n] : 0.f;
    }
    __syncthreads();
#pragma unroll
    for (int i = 0; i < 32; i += 8) {
        int n = n0 + y + i, c = c0 + x;
        if (n < Nc) {
            float v = tile[x][y + i];
            split16(v, dh[n * Cc + c], dl[n * Cc + c]);
        }
    }
}

// Z [bh][S][C] fp32 -> ZT [bh][C][S] single fp16
__global__ void k_vtrans() {
    __shared__ float t[32][33];
    int bh = blockIdx.z;
    int s0 = blockIdx.x * 32, c0 = blockIdx.y * 32;
    int x = threadIdx.x, y = threadIdx.y;
    const float* Z = g_Zf32 + (size_t)bh * Sc * Cc;
    fp16* th = gZT + (size_t)bh * Cc * Sc;
#pragma unroll
    for (int i = 0; i < 32; i += 8)
        t[y + i][x] = Z[(size_t)(s0 + y + i) * Cc + c0 + x];
    __syncthreads();
#pragma unroll
    for (int i = 0; i < 32; i += 8)
        th[(size_t)(c0 + y + i) * Sc + s0 + x] = __float2half(t[x][y + i]);
}

__global__ __launch_bounds__(256) void k_stats2() {
    int bh = blockIdx.x;
    float s = 0.f, q = 0.f;
    for (int i = threadIdx.x; i < NTILE; i += 256) {
        s += g_part[((size_t)bh * NTILE + i) * 2 + 0];
        q += g_part[((size_t)bh * NTILE + i) * 2 + 1];
    }
    __shared__ float ss[256], sq[256];
    int tid = threadIdx.x;
    ss[tid] = s; sq[tid] = q;
    __syncthreads();
    for (int st = 128; st > 0; st >>= 1) {
        if (tid < st) { ss[tid] += ss[tid + st]; sq[tid] += sq[tid + st]; }
        __syncthreads();
    }
    if (tid == 0) {
        float cnt = (float)Sc * (float)Sc;
        float mean = ss[0] / cnt;
        float var = sq[0] / cnt - mean * mean;
        g_mean[bh] = mean;
        g_rstd[bh] = rsqrtf(var + EPSc);
    }
}

// single-pass: p = exp2(a*s+b) in fp16 (unnormalized), row sums -> invsum
__global__ __launch_bounds__(256) void k_softmax1() {
    int row = blockIdx.x;
    int bh = row / Sc;
    size_t base = (size_t)row * Sc;
    float aa = g_rstd[bh] * LOG2E;
    float bb = -g_mean[bh] * g_rstd[bh] * LOG2E;
    const float2* src = (const float2*)(g_S + base);
    uint32_t* dst = (uint32_t*)(gP + base);
    float lsum = 0.f;
    for (int pi = threadIdx.x; pi < Sc / 2; pi += 256) {
        float2 s = src[pi];
        float z0 = fmaf(s.x, aa, bb);
        float z1 = fmaf(s.y, aa, bb);
        __half2 zh = __floats2half2_rn(z0, z1);
        uint32_t zi = *reinterpret_cast<uint32_t*>(&zh);
        uint32_t ei;
        asm("ex2.approx.f16x2 %0, %1;" : "=r"(ei) : "r"(zi));
        dst[pi] = ei;
        __half2 eh = *reinterpret_cast<__half2*>(&ei);
        float2 ef = __half22float2(eh);
        lsum += ef.x + ef.y;
    }
    __shared__ float red[256];
    int tid = threadIdx.x;
    red[tid] = lsum;
    __syncthreads();
    for (int st = 128; st > 0; st >>= 1) {
        if (tid < st) red[tid] += red[tid + st];
        __syncthreads();
    }
    if (tid == 0) g_invsum[row] = 1.f / red[0];
}

// out[b,s,d] = (1/H) sum_h invsum[bh,s] * (ctx1+ctx2)[bh,s,d]
__global__ __launch_bounds__(256) void k_out(float* __restrict__ out) {
    int idx = blockIdx.x * 256 + threadIdx.x;
    if (idx >= Bc * Sc * Cc) return;
    int b = idx / (Sc * Cc);
    int rem = idx % (Sc * Cc);
    int s = rem / Cc;
    float v = 0.f;
#pragma unroll
    for (int h = 0; h < Hc; h++) {
        int bh = b * Hc + h;
        size_t o = ((size_t)bh * Sc * Cc) + rem;
        v += (g_CTXH[o] + g_CTXH2[o]) * g_invsum[(size_t)bh * Sc + s];
    }
    out[idx] = 0.25f * v;
}

// ---------------- launch -------------------------------------------------------
extern "C" void kernel_launch(void* const* d_in, const int* in_sizes, int n_in,
                              void* d_out, int out_size) {
    const float* emb = (const float*)d_in[0];
    const float* Wq  = (const float*)d_in[1];
    const float* Wk  = (const float*)d_in[2];
    const float* Wv  = (const float*)d_in[3];
    const float* Wo  = (const float*)d_in[4];
    float* out = (float*)d_out;

    static bool attr_done = false;
    if (!attr_done) {
        cudaFuncSetAttribute(k_gemm_yz,  cudaFuncAttributeMaxDynamicSharedMemorySize, SMEM_GEMM);
        cudaFuncSetAttribute(k_gemm_sc,  cudaFuncAttributeMaxDynamicSharedMemorySize, SMEM_GEMM);
        cudaFuncSetAttribute(k_gemm_ctx, cudaFuncAttributeMaxDynamicSharedMemorySize, SMEM_GEMM);
        attr_done = true;
    }

    // input prep
    k_transpose<<<dim3(7, 8, Bc * Tc), dim3(32, 8)>>>(emb);
    k_gmat<<<dim3(16, 16, Hc), 256>>>(Wq, Wk);
    k_umat<<<dim3(16, 16, Hc), 256>>>(Wv, Wo);

    // Y and Z projections (N=256 single tile)
    k_gemm_yz<<<dim3(13, 1, 2 * BHc), 256, SMEM_GEMM>>>();
    // Z transpose -> fp16
    k_vtrans<<<dim3(49, 8, BHc), dim3(32, 8)>>>();
    // scores + fused stage-1 stats (m13 x n7)
    k_gemm_sc<<<dim3(13, 7, BHc), 256, SMEM_GEMM>>>();
    k_stats2<<<BHc, 256>>>();
    // norm + exp (fp16 probs, unnormalized) + row sums
    k_softmax1<<<BHc * Sc, 256>>>();
    // ctx = P @ Z^T (1-term, k-split x2)
    k_gemm_ctx<<<dim3(13, 1, BHc * 2), 256, SMEM_GEMM>>>();
    // final: head-mean, row normalization, straight into d_out
    k_out<<<(Bc * Sc * Cc + 255) / 256, 256>>>(out);
}

// round 9
// speedup vs baseline: 2.2423x; 1.4642x over previous
#include <cuda_runtime.h>
#include <cuda_fp16.h>
#include <cstdint>
#include <math.h>

// ---------------- problem constants ----------------
#define Bc 4
#define Tc 8
#define Cc 256
#define Nc 196
#define Hc 4
#define Sc (Tc * Nc)          // 1568
#define BHc (Bc * Hc)         // 16
#define EPSc 1e-5f
#define NTILE (13 * 13)       // score stat tiles per bh
#define LOG2E 1.4426950408889634f

typedef __half fp16;

// ---------------- scratch (device globals) ----------------------------------
__device__ fp16  g_Xhi[Bc * Sc * Cc];
__device__ fp16  g_Ghi[Hc * Cc * Cc];                          // G_h = Wk^T Wq (fp16)
__device__ fp16  g_Uhi[Hc * Cc * Cc],  g_Ulo[Hc * Cc * Cc];    // U_h = Wo Wv (split)
__device__ fp16  gY[BHc * Sc * Cc];                            // Y = Xhi G^T (fp16)
__device__ float g_Zf32[BHc * Sc * Cc];                        // Z = Xhi U^T
__device__ fp16  gZT[BHc * Cc * Sc];                           // Z^T fp16
__device__ fp16  g_S[(size_t)BHc * Sc * Sc];                   // fp16 scores
__device__ fp16  gP[(size_t)BHc * Sc * Sc];                    // unnormalized probs
__device__ float g_CTXH[BHc * Sc * Cc];                        // ctx k-half 0
__device__ float g_CTXH2[BHc * Sc * Cc];                       // ctx k-half 1
__device__ float g_invsum[BHc * Sc];
__device__ float g_part[BHc * NTILE * 2];
__device__ float g_mean[BHc], g_rstd[BHc];

// ---------------- PTX helpers ------------------------------------------------
__device__ __forceinline__ uint32_t cvta_smem(const void* p) {
    uint32_t a;
    asm("{ .reg .u64 t; cvta.to.shared.u64 t, %1; cvt.u32.u64 %0, t; }" : "=r"(a) : "l"(p));
    return a;
}

__device__ __forceinline__ void ldsm_x4(uint32_t& r0, uint32_t& r1, uint32_t& r2,
                                        uint32_t& r3, uint32_t addr) {
    asm volatile("ldmatrix.sync.aligned.m8n8.x4.shared.b16 {%0,%1,%2,%3}, [%4];"
                 : "=r"(r0), "=r"(r1), "=r"(r2), "=r"(r3) : "r"(addr));
}

__device__ __forceinline__ void mma16816(float* d, const uint32_t* a, const uint32_t* b) {
    asm volatile("mma.sync.aligned.m16n8k16.row.col.f32.f16.f16.f32 "
                 "{%0,%1,%2,%3}, {%4,%5,%6,%7}, {%8,%9}, {%0,%1,%2,%3};"
                 : "+f"(d[0]), "+f"(d[1]), "+f"(d[2]), "+f"(d[3])
                 : "r"(a[0]), "r"(a[1]), "r"(a[2]), "r"(a[3]), "r"(b[0]), "r"(b[1]));
}

__device__ __forceinline__ void cp16(uint32_t dst, const void* src, bool v) {
    asm volatile("cp.async.cg.shared.global [%0], [%1], 16, %2;"
                 :: "r"(dst), "l"(src), "r"(v ? 16u : 0u) : "memory");
}

__device__ __forceinline__ void split16(float v, fp16& h, fp16& l) {
    h = __float2half(v);
    l = __float2half(v - __half2float(h));
}

// ---------------- 128x128 fp16 HMMA GEMM, 3-stage, 64x32 warp tiles ----------
// NT form: C[m,n] = alpha * sum_k A[m,k]*B[n,k]; A,B row-major (k contiguous)
// NA terms x A arrays, NB x B arrays. Terms: Ahi*Bhi [+ Alo*Bhi] [+ Ahi*Blo]
#define EPI_F32    0
#define EPI_HALF   1
#define EPI_SCORES 2

#define KCH 32
#define ROWB 80                       // 64B data + 16B pad (conflict-free LDSM)
#define ARRB (128 * ROWB)             // 10240 B per operand array per stage
#define SM_ST 128
#define NSTAGE 3

template <int NA, int NB>
static __device__ __forceinline__ void gemm_body(
        const fp16* __restrict__ Ahi, const fp16* __restrict__ Alo,
        const fp16* __restrict__ Bhi, const fp16* __restrict__ Blo,
        int M, int N, int K, int lda, int ldb,
        int m0, int n0, int epi, float alpha,
        float* Cf, fp16* Ch, int ldc, float* part) {
    extern __shared__ char smem[];
    float* red = (float*)smem;
    const int tid = threadIdx.x;            // 256 threads, 8 warps (2m x 4n)
    const int wid = tid >> 5, lane = tid & 31;
    const int wm = (wid >> 2) * 64, wn = (wid & 3) * 32;
    const uint32_t sb = cvta_smem(smem);

    constexpr uint32_t OFA0 = 0;
    constexpr uint32_t OFA1 = ARRB;                 // valid when NA==2
    constexpr uint32_t OFB0 = NA * ARRB;
    constexpr uint32_t OFB1 = OFB0 + ARRB;          // valid when NB==2
    constexpr uint32_t STB = (NA + NB) * ARRB;      // bytes per stage

    float acc[4][4][4];
#pragma unroll
    for (int i = 0; i < 4; i++)
#pragma unroll
        for (int j = 0; j < 4; j++)
#pragma unroll
            for (int e = 0; e < 4; e++) acc[i][j][e] = 0.f;

    const int nch = K / KCH;

    #define ISSUE(ch)                                                            \
    do {                                                                         \
        const int k0_ = (ch) * KCH;                                              \
        const uint32_t stb_ = sb + SM_ST + ((ch) % NSTAGE) * STB;                \
        _Pragma("unroll")                                                        \
        for (int l = 0; l < 2; l++) {          /* A: 128 rows x 4 units */       \
            int it = tid + l * 256;                                              \
            int r = it >> 2, u = it & 3;                                         \
            bool av = (m0 + r) < M;                                              \
            size_t ao = av ? ((size_t)(m0 + r) * lda + k0_ + u * 8) : 0;         \
            uint32_t d = stb_ + OFA0 + r * ROWB + u * 16;                        \
            cp16(d, Ahi + ao, av);                                               \
            if (NA == 2) cp16(d + (OFA1 - OFA0), Alo + ao, av);                  \
        }                                                                        \
        _Pragma("unroll")                                                        \
        for (int l = 0; l < 2; l++) {          /* B: 128 rows x 4 units */       \
            int it = tid + l * 256;                                              \
            int r = it >> 2, u = it & 3;                                         \
            bool bv = (n0 + r) < N;                                              \
            size_t bo = bv ? ((size_t)(n0 + r) * ldb + k0_ + u * 8) : 0;         \
            uint32_t d = stb_ + OFB0 + r * ROWB + u * 16;                        \
            cp16(d, Bhi + bo, bv);                                               \
            if (NB == 2) cp16(d + (OFB1 - OFB0), Blo + bo, bv);                  \
        }                                                                        \
    } while (0)

    ISSUE(0);
    asm volatile("cp.async.commit_group;" ::: "memory");
    if (nch > 1) ISSUE(1);
    asm volatile("cp.async.commit_group;" ::: "memory");

    const uint32_t lrow = (uint32_t)(lane & 15);
    const uint32_t lu = (uint32_t)(lane >> 4);

    for (int ch = 0; ch < nch; ch++) {
        if (ch < nch - 1) {
            asm volatile("cp.async.wait_group 1;" ::: "memory");
        } else {
            asm volatile("cp.async.wait_group 0;" ::: "memory");
        }
        __syncthreads();
        if (ch + 2 < nch) {
            ISSUE(ch + 2);
            asm volatile("cp.async.commit_group;" ::: "memory");
        }

        const uint32_t stb = sb + SM_ST + (ch % NSTAGE) * STB;
#pragma unroll
        for (int ku = 0; ku < 2; ku++) {
            const uint32_t koffb = ku * 32 + lu * 16;
            uint32_t af[4][4];
            uint32_t bfr[4][2];

            // A-hi frags (4 m16 tiles)
#pragma unroll
            for (int im = 0; im < 4; im++) {
                uint32_t addr = stb + OFA0 + (wm + im * 16 + lrow) * ROWB + koffb;
                ldsm_x4(af[im][0], af[im][1], af[im][2], af[im][3], addr);
            }
            // B-hi frags (2 n16 tiles -> 4 n8 frags)
#pragma unroll
            for (int inn = 0; inn < 2; inn++) {
                uint32_t addr = stb + OFB0 + (wn + inn * 16 + lrow) * ROWB + koffb;
                uint32_t r0, r1, r2, r3;
                ldsm_x4(r0, r1, r2, r3, addr);
                bfr[inn * 2 + 0][0] = r0; bfr[inn * 2 + 0][1] = r2;
                bfr[inn * 2 + 1][0] = r1; bfr[inn * 2 + 1][1] = r3;
            }
            // term: Ahi x Bhi
#pragma unroll
            for (int im = 0; im < 4; im++)
#pragma unroll
                for (int jn = 0; jn < 4; jn++) mma16816(acc[im][jn], af[im], bfr[jn]);

            if (NA == 2) {   // term: Alo x Bhi
#pragma unroll
                for (int im = 0; im < 4; im++) {
                    uint32_t addr = stb + OFA1 + (wm + im * 16 + lrow) * ROWB + koffb;
                    ldsm_x4(af[im][0], af[im][1], af[im][2], af[im][3], addr);
                }
#pragma unroll
                for (int im = 0; im < 4; im++)
#pragma unroll
                    for (int jn = 0; jn < 4; jn++) mma16816(acc[im][jn], af[im], bfr[jn]);
            }
            if (NB == 2) {   // term: Ahi x Blo (af must hold Ahi)
                if (NA == 2) {
#pragma unroll
                    for (int im = 0; im < 4; im++) {
                        uint32_t addr = stb + OFA0 + (wm + im * 16 + lrow) * ROWB + koffb;
                        ldsm_x4(af[im][0], af[im][1], af[im][2], af[im][3], addr);
                    }
                }
#pragma unroll
                for (int inn = 0; inn < 2; inn++) {
                    uint32_t addr = stb + OFB1 + (wn + inn * 16 + lrow) * ROWB + koffb;
                    uint32_t r0, r1, r2, r3;
                    ldsm_x4(r0, r1, r2, r3, addr);
                    bfr[inn * 2 + 0][0] = r0; bfr[inn * 2 + 0][1] = r2;
                    bfr[inn * 2 + 1][0] = r1; bfr[inn * 2 + 1][1] = r3;
                }
#pragma unroll
                for (int im = 0; im < 4; im++)
#pragma unroll
                    for (int jn = 0; jn < 4; jn++) mma16816(acc[im][jn], af[im], bfr[jn]);
            }
        }
    }
    #undef ISSUE

    // ---------------- epilogue ----------------
    float psum = 0.f, psq = 0.f;
#pragma unroll
    for (int im = 0; im < 4; im++) {
#pragma unroll
        for (int jn = 0; jn < 4; jn++) {
            int r0 = m0 + wm + im * 16 + (lane >> 2);
            int cn = n0 + wn + jn * 8 + (lane & 3) * 2;
            bool cv = cn < N;
            float v0 = acc[im][jn][0] * alpha, v1 = acc[im][jn][1] * alpha;
            float v2 = acc[im][jn][2] * alpha, v3 = acc[im][jn][3] * alpha;
            if (epi == EPI_F32) {
                if (cv && r0 < M)
                    *(float2*)&Cf[(size_t)r0 * ldc + cn] = make_float2(v0, v1);
                if (cv && r0 + 8 < M)
                    *(float2*)&Cf[(size_t)(r0 + 8) * ldc + cn] = make_float2(v2, v3);
            } else {
                if (cv && r0 < M) {
                    __half2 hh; hh.x = __float2half(v0); hh.y = __float2half(v1);
                    *(__half2*)&Ch[(size_t)r0 * ldc + cn] = hh;
                    if (epi == EPI_SCORES) { psum += v0 + v1; psq += v0 * v0 + v1 * v1; }
                }
                if (cv && r0 + 8 < M) {
                    __half2 hh; hh.x = __float2half(v2); hh.y = __float2half(v3);
                    *(__half2*)&Ch[(size_t)(r0 + 8) * ldc + cn] = hh;
                    if (epi == EPI_SCORES) { psum += v2 + v3; psq += v2 * v2 + v3 * v3; }
                }
            }
        }
    }
    if (epi == EPI_SCORES) {
#pragma unroll
        for (int o = 16; o; o >>= 1) {
            psum += __shfl_xor_sync(0xffffffffu, psum, o);
            psq  += __shfl_xor_sync(0xffffffffu, psq,  o);
        }
        if (lane == 0) { red[wid] = psum; red[8 + wid] = psq; }
        __syncthreads();
        if (tid == 0) {
            float s = 0.f, q = 0.f;
#pragma unroll
            for (int w = 0; w < 8; w++) { s += red[w]; q += red[8 + w]; }
            part[0] = s;
            part[1] = q;
        }
    }
}

#define SMEM_11 (SM_ST + NSTAGE * 2 * ARRB)   // 61568
#define SMEM_12 (SM_ST + NSTAGE * 3 * ARRB)   // 92288

// ---------------- GEMM wrappers ----------------------------------------------
// Y = Xhi G^T (1-term, fp16 out)
__global__ __launch_bounds__(256, 2) void k_gemm_y() {
    int bh = blockIdx.z;
    int b = bh / Hc, h = bh % Hc;
    gemm_body<1, 1>(g_Xhi + (size_t)b * Sc * Cc, nullptr,
                    g_Ghi + (size_t)h * Cc * Cc, nullptr,
                    Sc, Cc, Cc, Cc, Cc, blockIdx.x * 128, blockIdx.y * 128,
                    EPI_HALF, 1.f, nullptr, gY + (size_t)bh * Sc * Cc, Cc, nullptr);
}

// Z = Xhi (Uhi+Ulo)^T (2-term, f32 out)
__global__ __launch_bounds__(256, 2) void k_gemm_z() {
    int bh = blockIdx.z;
    int b = bh / Hc, h = bh % Hc;
    gemm_body<1, 2>(g_Xhi + (size_t)b * Sc * Cc, nullptr,
                    g_Uhi + (size_t)h * Cc * Cc, g_Ulo + (size_t)h * Cc * Cc,
                    Sc, Cc, Cc, Cc, Cc, blockIdx.x * 128, blockIdx.y * 128,
                    EPI_F32, 1.f, g_Zf32 + (size_t)bh * Sc * Cc, nullptr, Cc, nullptr);
}

// scores = Y Xhi^T / sqrt(S) (1-term, fp16 out + stats)
__global__ __launch_bounds__(256, 2) void k_gemm_sc() {
    int bh = blockIdx.z;
    int b = bh / Hc;
    float alpha = rsqrtf((float)Sc);
    gemm_body<1, 1>(gY + (size_t)bh * Sc * Cc, nullptr,
                    g_Xhi + (size_t)b * Sc * Cc, nullptr,
                    Sc, Sc, Cc, Cc, Cc, blockIdx.x * 128, blockIdx.y * 128,
                    EPI_SCORES, alpha, nullptr, g_S + (size_t)bh * Sc * Sc, Sc,
                    &g_part[((size_t)bh * NTILE + blockIdx.y * 13 + blockIdx.x) * 2]);
}

// ctx = P @ Z^T (1-term, f32 out), K-split [0,768)/[768,1568)
__global__ __launch_bounds__(256, 2) void k_gemm_ctx() {
    int z = blockIdx.z;
    int bh = z >> 1, half = z & 1;
    int koff = half ? 768 : 0;
    int klen = half ? (Sc - 768) : 768;
    float* outbuf = (half ? g_CTXH2 : g_CTXH) + (size_t)bh * Sc * Cc;
    gemm_body<1, 1>(gP + (size_t)bh * Sc * Sc + koff, nullptr,
                    gZT + (size_t)bh * Cc * Sc + koff, nullptr,
                    Sc, Cc, klen, Sc, Sc, blockIdx.x * 128, blockIdx.y * 128,
                    EPI_F32, 1.f, outbuf, nullptr, Cc, nullptr);
}

// ---------------- small fp32 weight-product kernels ---------------------------
__global__ __launch_bounds__(256) void k_gmat(const float* __restrict__ Wq,
                                              const float* __restrict__ Wk) {
    int h = blockIdx.z;
    int a0 = blockIdx.x * 16, b0 = blockIdx.y * 16;
    int tx = threadIdx.x & 15, ty = threadIdx.x >> 4;
    __shared__ float A[16][17], B[16][17];
    const float* wk = Wk + (size_t)h * Cc * Cc;
    const float* wq = Wq + (size_t)h * Cc * Cc;
    float acc = 0.f;
    for (int d0 = 0; d0 < Cc; d0 += 16) {
        A[ty][tx] = wk[(d0 + ty) * Cc + a0 + tx];
        B[ty][tx] = wq[(d0 + ty) * Cc + b0 + tx];
        __syncthreads();
#pragma unroll
        for (int dd = 0; dd < 16; dd++) acc += A[dd][ty] * B[dd][tx];
        __syncthreads();
    }
    g_Ghi[(size_t)h * Cc * Cc + (a0 + ty) * Cc + b0 + tx] = __float2half(acc);
}

__global__ __launch_bounds__(256) void k_umat(const float* __restrict__ Wv,
                                              const float* __restrict__ Wo) {
    int h = blockIdx.z;
    int a0 = blockIdx.x * 16, b0 = blockIdx.y * 16;
    int tx = threadIdx.x & 15, ty = threadIdx.x >> 4;
    __shared__ float A[16][17], B[16][17];
    const float* wv = Wv + (size_t)h * Cc * Cc;
    float acc = 0.f;
    for (int d0 = 0; d0 < Cc; d0 += 16) {
        A[ty][tx] = Wo[(a0 + ty) * Cc + d0 + tx];
        B[ty][tx] = wv[(d0 + ty) * Cc + b0 + tx];
        __syncthreads();
#pragma unroll
        for (int dd = 0; dd < 16; dd++) acc += A[ty][dd] * B[dd][tx];
        __syncthreads();
    }
    size_t o = (size_t)h * Cc * Cc + (a0 + ty) * Cc + b0 + tx;
    split16(acc, g_Uhi[o], g_Ulo[o]);
}

// ---------------- elementwise / reshape kernels -------------------------------
__global__ void k_transpose(const float* __restrict__ emb) {
    __shared__ float tile[32][33];
    int bt = blockIdx.z;
    int n0 = blockIdx.x * 32, c0 = blockIdx.y * 32;
    int x = threadIdx.x, y = threadIdx.y;
    const float* src = emb + (size_t)bt * Cc * Nc;
    fp16* dh = g_Xhi + (size_t)bt * Nc * Cc;
#pragma unroll
    for (int i = 0; i < 32; i += 8) {
        int c = c0 + y + i, n = n0 + x;
        tile[y + i][x] = (n < Nc) ? src[c * Nc + n] : 0.f;
    }
    __syncthreads();
#pragma unroll
    for (int i = 0; i < 32; i += 8) {
        int n = n0 + y + i, c = c0 + x;
        if (n < Nc) dh[n * Cc + c] = __float2half(tile[x][y + i]);
    }
}

// Z [bh][S][C] fp32 -> ZT [bh][C][S] fp16
__global__ void k_vtrans() {
    __shared__ float t[32][33];
    int bh = blockIdx.z;
    int s0 = blockIdx.x * 32, c0 = blockIdx.y * 32;
    int x = threadIdx.x, y = threadIdx.y;
    const float* Z = g_Zf32 + (size_t)bh * Sc * Cc;
    fp16* th = gZT + (size_t)bh * Cc * Sc;
#pragma unroll
    for (int i = 0; i < 32; i += 8)
        t[y + i][x] = Z[(size_t)(s0 + y + i) * Cc + c0 + x];
    __syncthreads();
#pragma unroll
    for (int i = 0; i < 32; i += 8)
        th[(size_t)(c0 + y + i) * Sc + s0 + x] = __float2half(t[x][y + i]);
}

__global__ __launch_bounds__(256) void k_stats2() {
    int bh = blockIdx.x;
    float s = 0.f, q = 0.f;
    for (int i = threadIdx.x; i < NTILE; i += 256) {
        s += g_part[((size_t)bh * NTILE + i) * 2 + 0];
        q += g_part[((size_t)bh * NTILE + i) * 2 + 1];
    }
    __shared__ float ss[256], sq[256];
    int tid = threadIdx.x;
    ss[tid] = s; sq[tid] = q;
    __syncthreads();
    for (int st = 128; st > 0; st >>= 1) {
        if (tid < st) { ss[tid] += ss[tid + st]; sq[tid] += sq[tid + st]; }
        __syncthreads();
    }
    if (tid == 0) {
        float cnt = (float)Sc * (float)Sc;
        float mean = ss[0] / cnt;
        float var = sq[0] / cnt - mean * mean;
        g_mean[bh] = mean;
        g_rstd[bh] = rsqrtf(var + EPSc);
    }
}

// single-pass: p = exp2(a*s+b) in fp16 (unnormalized), row sums -> invsum
__global__ __launch_bounds__(256) void k_softmax1() {
    int row = blockIdx.x;
    int bh = row / Sc;
    size_t base = (size_t)row * Sc;
    float aa = g_rstd[bh] * LOG2E;
    float bb = -g_mean[bh] * g_rstd[bh] * LOG2E;
    const __half2* src = (const __half2*)(g_S + base);
    uint32_t* dst = (uint32_t*)(gP + base);
    float lsum = 0.f;
    for (int pi = threadIdx.x; pi < Sc / 2; pi += 256) {
        float2 s = __half22float2(src[pi]);
        float z0 = fmaf(s.x, aa, bb);
        float z1 = fmaf(s.y, aa, bb);
        __half2 zh = __floats2half2_rn(z0, z1);
        uint32_t zi = *reinterpret_cast<uint32_t*>(&zh);
        uint32_t ei;
        asm("ex2.approx.f16x2 %0, %1;" : "=r"(ei) : "r"(zi));
        dst[pi] = ei;
        __half2 eh = *reinterpret_cast<__half2*>(&ei);
        float2 ef = __half22float2(eh);
        lsum += ef.x + ef.y;
    }
    __shared__ float red[256];
    int tid = threadIdx.x;
    red[tid] = lsum;
    __syncthreads();
    for (int st = 128; st > 0; st >>= 1) {
        if (tid < st) red[tid] += red[tid + st];
        __syncthreads();
    }
    if (tid == 0) g_invsum[row] = 1.f / red[0];
}

// out[b,s,d] = (1/H) sum_h invsum[bh,s] * (ctx1+ctx2)[bh,s,d]
__global__ __launch_bounds__(256) void k_out(float* __restrict__ out) {
    int idx = blockIdx.x * 256 + threadIdx.x;
    if (idx >= Bc * Sc * Cc) return;
    int b = idx / (Sc * Cc);
    int rem = idx % (Sc * Cc);
    int s = rem / Cc;
    float v = 0.f;
#pragma unroll
    for (int h = 0; h < Hc; h++) {
        int bh = b * Hc + h;
        size_t o = ((size_t)bh * Sc * Cc) + rem;
        v += (g_CTXH[o] + g_CTXH2[o]) * g_invsum[(size_t)bh * Sc + s];
    }
    out[idx] = 0.25f * v;
}

// ---------------- launch -------------------------------------------------------
extern "C" void kernel_launch(void* const* d_in, const int* in_sizes, int n_in,
                              void* d_out, int out_size) {
    const float* emb = (const float*)d_in[0];
    const float* Wq  = (const float*)d_in[1];
    const float* Wk  = (const float*)d_in[2];
    const float* Wv  = (const float*)d_in[3];
    const float* Wo  = (const float*)d_in[4];
    float* out = (float*)d_out;

    static bool attr_done = false;
    if (!attr_done) {
        cudaFuncSetAttribute(k_gemm_y,   cudaFuncAttributeMaxDynamicSharedMemorySize, SMEM_11);
        cudaFuncSetAttribute(k_gemm_z,   cudaFuncAttributeMaxDynamicSharedMemorySize, SMEM_12);
        cudaFuncSetAttribute(k_gemm_sc,  cudaFuncAttributeMaxDynamicSharedMemorySize, SMEM_11);
        cudaFuncSetAttribute(k_gemm_ctx, cudaFuncAttributeMaxDynamicSharedMemorySize, SMEM_11);
        attr_done = true;
    }

    // input prep
    k_transpose<<<dim3(7, 8, Bc * Tc), dim3(32, 8)>>>(emb);
    k_gmat<<<dim3(16, 16, Hc), 256>>>(Wq, Wk);
    k_umat<<<dim3(16, 16, Hc), 256>>>(Wv, Wo);

    // Y and Z projections
    k_gemm_y<<<dim3(13, 2, BHc), 256, SMEM_11>>>();
    k_gemm_z<<<dim3(13, 2, BHc), 256, SMEM_12>>>();
    // Z transpose -> fp16
    k_vtrans<<<dim3(49, 8, BHc), dim3(32, 8)>>>();
    // scores (fp16) + fused stage-1 stats
    k_gemm_sc<<<dim3(13, 13, BHc), 256, SMEM_11>>>();
    k_stats2<<<BHc, 256>>>();
    // norm + exp (fp16 probs, unnormalized) + row sums
    k_softmax1<<<BHc * Sc, 256>>>();
    // ctx = P @ Z^T (k-split x2)
    k_gemm_ctx<<<dim3(13, 2, BHc * 2), 256, SMEM_11>>>();
    // final: head-mean, row normalization, straight into d_out
    k_out<<<(Bc * Sc * Cc + 255) / 256, 256>>>(out);
}